// round 13
// baseline (speedup 1.0000x reference)
#include <cuda_runtime.h>
#include <cuda_fp16.h>
#include <cstdint>
#include <cstddef>

// Problem constants
#define BB    2
#define SS    2048
#define DD    768
#define HH    12
#define HDD   64
#define DFF   3072
#define NROW  4096            // B*S

// GEMM tiling: 128x128 CTA tile, K chunks of 32, tiled global layout.
#define CH     32
#define PADC   40
#define TILE_HW 5120
#define TILE_B  10240
#define G_STAGE_B (2 * TILE_B)             // A + B (single-pass fp16)
#define GEMM_SMEM (3 * G_STAGE_B + 64)     // 3 stages + mbarriers

#define TSZ(R, K) ((size_t)(R) * (K) / 32 * 40)

// ---------------------------------------------------------------------------
// Scratch (device globals)
// ---------------------------------------------------------------------------
__device__ float g_res1[NROW * DD];
__device__ float g_y[NROW * DD];
__device__ float g_z[NROW * DD];

// tiled fp16 activations
__device__ __half g_xh[TSZ(NROW, DD)];
__device__ __half g_ath[TSZ(NROW, DD)];
__device__ __half g_yh[TSZ(NROW, DD)];
__device__ __half g_h1h[TSZ(NROW, DFF)];

// head-major fp16 q/k/v (linear) + per-head transposed V
__device__ __half g_qh[BB*HH*SS*HDD];
__device__ __half g_kh[BB*HH*SS*HDD];
__device__ __half g_vh[BB*HH*SS*HDD];
__device__ __half g_vt[BB*HH*SS*HDD];     // [bh][hd][s]

// tiled fp16 transposed weights [N, K]
__device__ __half g_wqT[TSZ(DD, DD)];
__device__ __half g_wkT[TSZ(DD, DD)];
__device__ __half g_wvT[TSZ(DD, DD)];
__device__ __half g_woT[TSZ(DD, DD)];
__device__ __half g_w1T[TSZ(DFF, DD)];
__device__ __half g_w2T[TSZ(DD, DFF)];

// ---------------------------------------------------------------------------
// helpers
// ---------------------------------------------------------------------------
__device__ __forceinline__ uint32_t smem_u32(const void* p) {
    uint32_t a;
    asm("{ .reg .u64 t; cvta.to.shared.u64 t, %1; cvt.u32.u64 %0, t; }"
        : "=r"(a) : "l"(p));
    return a;
}
__device__ __forceinline__ void mma16816h(float* d, const uint32_t* a,
                                          uint32_t b0, uint32_t b1) {
    asm volatile(
        "mma.sync.aligned.m16n8k16.row.col.f32.f16.f16.f32 "
        "{%0,%1,%2,%3}, {%4,%5,%6,%7}, {%8,%9}, {%0,%1,%2,%3};"
        : "+f"(d[0]), "+f"(d[1]), "+f"(d[2]), "+f"(d[3])
        : "r"(a[0]), "r"(a[1]), "r"(a[2]), "r"(a[3]), "r"(b0), "r"(b1));
}
__device__ __forceinline__ uint32_t pack_f16(float lo, float hi) {
    uint32_t r;
    asm("cvt.rn.f16x2.f32 %0, %1, %2;" : "=r"(r) : "f"(hi), "f"(lo));
    return r;
}
__device__ __forceinline__ void ldmx4(uint32_t* r, uint32_t addr) {
    asm volatile("ldmatrix.sync.aligned.m8n8.x4.shared.b16 {%0,%1,%2,%3}, [%4];"
                 : "=r"(r[0]), "=r"(r[1]), "=r"(r[2]), "=r"(r[3]) : "r"(addr));
}
__device__ __forceinline__ void mbar_init(uint32_t mbar, uint32_t cnt) {
    asm volatile("mbarrier.init.shared.b64 [%0], %1;" :: "r"(mbar), "r"(cnt) : "memory");
}
__device__ __forceinline__ void mbar_wait(uint32_t mbar, uint32_t parity) {
    asm volatile(
        "{\n\t.reg .pred P;\n\t"
        "WL_%=:\n\t"
        "mbarrier.try_wait.parity.acquire.cta.shared::cta.b64 P, [%0], %1, 0x989680;\n\t"
        "@P bra.uni WD_%=;\n\t"
        "bra.uni WL_%=;\n\t"
        "WD_%=:\n\t}"
        :: "r"(mbar), "r"(parity) : "memory");
}
__device__ __forceinline__ void mbar_expect_tx(uint32_t mbar, uint32_t bytes) {
    asm volatile("mbarrier.arrive.expect_tx.shared.b64 _, [%0], %1;"
                 :: "r"(mbar), "r"(bytes) : "memory");
}
__device__ __forceinline__ void bulkcp(uint32_t dst, const void* src,
                                       uint32_t bytes, uint32_t mbar) {
    asm volatile(
        "cp.async.bulk.shared::cta.global.mbarrier::complete_tx::bytes "
        "[%0], [%1], %2, [%3];"
        :: "r"(dst), "l"(src), "r"(bytes), "r"(mbar) : "memory");
}
__device__ __forceinline__ void cp16(uint32_t dst, const void* src) {
    asm volatile("cp.async.cg.shared.global [%0], [%1], 16;"
                 :: "r"(dst), "l"(src));
}
__device__ __forceinline__ void cp_commit() { asm volatile("cp.async.commit_group;"); }
__device__ __forceinline__ void cp_wait0()  { asm volatile("cp.async.wait_group 0;"); }
__device__ __forceinline__ void cp_wait1()  { asm volatile("cp.async.wait_group 1;"); }

__device__ __forceinline__ size_t toff(int row, int col, int kcn) {
    return (size_t)((row >> 7) * kcn + (col >> 5)) * TILE_HW +
           (row & 127) * PADC + (col & 31);
}

// ---------------------------------------------------------------------------
// fp32 [4096,768] -> tiled fp16
// ---------------------------------------------------------------------------
__global__ void __launch_bounds__(256) convert_h(
    const float* __restrict__ in, __half* __restrict__ oh)
{
    const int i = blockIdx.x * 256 + threadIdx.x;
    const int e = 4 * i;
    const int row = e / DD, col = e - row * DD;
    float4 v = ((const float4*)in)[i];
    const size_t o = toff(row, col, DD / 32);
    *(uint2*)(oh + o) = make_uint2(pack_f16(v.x, v.y), pack_f16(v.z, v.w));
}

// ---------------------------------------------------------------------------
// Fused 4x: W[768,768] fp32 -> tiled Wt[768,768] fp16 (blockIdx.z selects)
// ---------------------------------------------------------------------------
struct T4 { const float* W[4]; __half* T[4]; };

__global__ void __launch_bounds__(256) transpose4_h(T4 p)
{
    __shared__ float tile[32][33];
    const float* W = p.W[blockIdx.z];
    __half* T = p.T[blockIdx.z];
    const int k0 = blockIdx.y * 32, n0 = blockIdx.x * 32;
    const int tx = threadIdx.x, ty = threadIdx.y;   // (32, 8)
#pragma unroll
    for (int i = 0; i < 4; i++)
        tile[ty + 8 * i][tx] = W[(size_t)(k0 + ty + 8 * i) * DD + n0 + tx];
    __syncthreads();
#pragma unroll
    for (int i = 0; i < 4; i++)
        T[toff(n0 + ty + 8 * i, k0 + tx, DD >> 5)] =
            __float2half_rn(tile[tx][ty + 8 * i]);
}

// generic single transpose (W1 / W2)
__global__ void __launch_bounds__(256) transpose_h(
    const float* __restrict__ W, __half* __restrict__ T, int K, int N)
{
    __shared__ float tile[32][33];
    const int k0 = blockIdx.y * 32, n0 = blockIdx.x * 32;
    const int tx = threadIdx.x, ty = threadIdx.y;
#pragma unroll
    for (int i = 0; i < 4; i++)
        tile[ty + 8 * i][tx] = W[(size_t)(k0 + ty + 8 * i) * N + n0 + tx];
    __syncthreads();
    const int kcn = K >> 5;
#pragma unroll
    for (int i = 0; i < 4; i++)
        T[toff(n0 + ty + 8 * i, k0 + tx, kcn)] =
            __float2half_rn(tile[tx][ty + 8 * i]);
}

// ---------------------------------------------------------------------------
// per-head V transpose: [s, hd] -> [hd, s] (fp16, linear)
// ---------------------------------------------------------------------------
__global__ void __launch_bounds__(256) vtrans_h(
    const __half* __restrict__ in, __half* __restrict__ out)
{
    __shared__ uint16_t sm[64][72];
    const int s0 = blockIdx.x * 64;
    const size_t bh = blockIdx.y;
    const uint16_t* src = (const uint16_t*)(in + bh * SS * HDD);
    uint16_t* dst = (uint16_t*)(out + bh * (size_t)HDD * SS);
    const int t = threadIdx.x;
    const int r = t >> 2, cq = (t & 3) * 16;
    *(uint4*)(&sm[r][cq])     = *(const uint4*)(src + (size_t)(s0 + r) * HDD + cq);
    *(uint4*)(&sm[r][cq + 8]) = *(const uint4*)(src + (size_t)(s0 + r) * HDD + cq + 8);
    __syncthreads();
    uint32_t w[8];
#pragma unroll
    for (int j = 0; j < 8; j++)
        w[j] = ((uint32_t)sm[cq + 2 * j + 1][r] << 16) | sm[cq + 2 * j][r];
#pragma unroll
    for (int j = 0; j < 4; j++)
        *(uint2*)(dst + (size_t)r * SS + s0 + cq + 4 * j) =
            make_uint2(w[2 * j], w[2 * j + 1]);
}

// ---------------------------------------------------------------------------
// fp16 1-pass GEMM (R10 proven): 128x128 tile, 8 warps 4(M)x2(N),
// 3-stage bulk-DMA pipeline.
// ---------------------------------------------------------------------------
#define M_QKV 0
#define M_WO  1
#define M_FF1 2
#define M_FF2 3

struct PtrQ {
    const __half* b;
    const float* bias;
    __half* c;            // fp16 linear head-major
};
struct Qkv3 { PtrQ p[3]; };

template <int MODE>
__global__ void __launch_bounds__(256) gemm_h(
    const __half* __restrict__ A, const __half* __restrict__ B_,
    const float* __restrict__ bias_, const float* __restrict__ res,
    float* __restrict__ Cf, __half* __restrict__ Ch_,
    Qkv3 qkv, int M, int N, int K)
{
    extern __shared__ char smem[];
    const uint32_t sb = smem_u32(smem);
    const uint32_t mbb = sb + 3 * G_STAGE_B;

    const int t    = threadIdx.x;
    const int lane = t & 31, wid = t >> 5;
    const int wm   = (wid & 3) * 32;
    const int wn   = (wid >> 2) * 64;
    const int bm   = blockIdx.y * 128, bn = blockIdx.x * 128;
    const int g    = lane >> 2, tig = lane & 3;

    const __half* B;
    const float* bias;
    __half* Ch = Ch_;
    if (MODE == M_QKV) {
        const PtrQ& p = qkv.p[blockIdx.z];
        B = p.b; bias = p.bias; Ch = p.c;
    } else {
        B = B_; bias = bias_;
    }

    if (t == 0) { mbar_init(mbb, 1); mbar_init(mbb + 8, 1); mbar_init(mbb + 16, 1); }
    __syncthreads();

    float acc[2][8][4];
#pragma unroll
    for (int i = 0; i < 2; i++)
#pragma unroll
        for (int j = 0; j < 8; j++)
#pragma unroll
            for (int c = 0; c < 4; c++) acc[i][j][c] = 0.f;

    const int KCN = K >> 5;
    const int arb = bm >> 7, brb = bn >> 7;

    auto issue = [&](int c, int stage) {
        if (t == 0) {
            const uint32_t mbar = mbb + stage * 8;
            mbar_expect_tx(mbar, G_STAGE_B);
            const uint32_t d = sb + stage * G_STAGE_B;
            bulkcp(d,          A + ((size_t)arb * KCN + c) * TILE_HW, TILE_B, mbar);
            bulkcp(d + TILE_B, B + ((size_t)brb * KCN + c) * TILE_HW, TILE_B, mbar);
        }
    };

    uint32_t ph[3] = {0, 0, 0};
    issue(0, 0);
    if (KCN > 1) issue(1, 1);

    const uint32_t lrow = (uint32_t)(lane & 15);
    const uint32_t lcol = (uint32_t)((lane >> 4) * 8);

    for (int c = 0; c < KCN; c++) {
        if (c + 2 < KCN) issue(c + 2, (c + 2) % 3);
        const int st = c % 3;
        mbar_wait(mbb + st * 8, ph[st]);
        ph[st] ^= 1;

        const uint32_t sA = sb + st * G_STAGE_B;
        const uint32_t sB = sA + TILE_B;

#pragma unroll
        for (int kk = 0; kk < CH; kk += 16) {
            uint32_t a[2][4];
            ldmx4(a[0], sA + ((wm + lrow) * PADC + kk + lcol) * 2);
            ldmx4(a[1], sA + ((wm + 16 + lrow) * PADC + kk + lcol) * 2);
#pragma unroll
            for (int p = 0; p < 4; p++) {
                uint32_t bf[4];
                ldmx4(bf, sB + ((wn + 16 * p + lrow) * PADC + kk + lcol) * 2);
#pragma unroll
                for (int q = 0; q < 2; q++) {
                    const int nt = 2 * p + q;
                    mma16816h(acc[0][nt], a[0], bf[q], bf[q + 2]);
                    mma16816h(acc[1][nt], a[1], bf[q], bf[q + 2]);
                }
            }
        }
        __syncthreads();
    }

    const int okcn = N >> 5;
#pragma unroll
    for (int mt = 0; mt < 2; mt++) {
#pragma unroll
        for (int nt = 0; nt < 8; nt++) {
#pragma unroll
            for (int half = 0; half < 2; half++) {
                const int grow = bm + wm + mt * 16 + g + half * 8;
                const int gcol = bn + wn + nt * 8 + 2 * tig;
                float v0 = acc[mt][nt][half * 2 + 0] + bias[gcol];
                float v1 = acc[mt][nt][half * 2 + 1] + bias[gcol + 1];
                if (MODE == M_QKV) {
                    const int b_ = grow >> 11, s_ = grow & 2047;
                    const int h_ = gcol >> 6,  hd = gcol & 63;
                    *(uint32_t*)(Ch + (((size_t)(b_ * HH + h_) * SS) + s_) * HDD + hd) =
                        pack_f16(v0, v1);
                } else if (MODE == M_FF1) {
                    v0 = fmaxf(v0, 0.f);
                    v1 = fmaxf(v1, 0.f);
                    *(uint32_t*)(Ch + toff(grow, gcol, okcn)) = pack_f16(v0, v1);
                } else {
                    const size_t o = (size_t)grow * N + gcol;
                    v0 += res[o];
                    v1 += res[o + 1];
                    *(float2*)(Cf + o) = make_float2(v0, v1);
                }
            }
        }
    }
}

// ---------------------------------------------------------------------------
// fp16 1-pass tensor-core flash attention (R10 proven, unchanged)
// ---------------------------------------------------------------------------
__global__ void __launch_bounds__(128) attn_tc(
    const float* __restrict__ alibi,
    const __half* __restrict__ Q, const __half* __restrict__ K,
    const __half* __restrict__ Vt, __half* __restrict__ O)
{
    __shared__ __half sk[2][64 * 72];
    __shared__ __half sv[2][64 * 72];

    const int t = threadIdx.x, lane = t & 31, wid = t >> 5;
    const int g = lane >> 2, tig = lane & 3;
    const int qt = (int)(gridDim.x - 1) - (int)blockIdx.x;
    const int h = blockIdx.y, b = blockIdx.z;
    const int q0 = qt * 128, wm = wid * 32;
    const size_t bh = (size_t)(b * HH + h);

    const __half* qb = Q + (bh * SS + q0) * HDD;
    const __half* kb = K + bh * SS * HDD;
    const __half* vb = Vt + bh * (size_t)HDD * SS;
    const float* ab = alibi + (size_t)h * SS * SS;

    uint32_t qf[4][2][4];
#pragma unroll
    for (int kc = 0; kc < 4; kc++)
#pragma unroll
        for (int mt = 0; mt < 2; mt++) {
            const int row = wm + mt * 16 + g;
            qf[kc][mt][0] = *(const uint32_t*)(qb + (size_t)row * HDD + kc * 16 + 2 * tig);
            qf[kc][mt][1] = *(const uint32_t*)(qb + (size_t)(row + 8) * HDD + kc * 16 + 2 * tig);
            qf[kc][mt][2] = *(const uint32_t*)(qb + (size_t)row * HDD + kc * 16 + 8 + 2 * tig);
            qf[kc][mt][3] = *(const uint32_t*)(qb + (size_t)(row + 8) * HDD + kc * 16 + 8 + 2 * tig);
        }

    float o[2][8][4];
#pragma unroll
    for (int i = 0; i < 2; i++)
#pragma unroll
        for (int j = 0; j < 8; j++)
#pragma unroll
            for (int c = 0; c < 4; c++) o[i][j][c] = 0.f;
    float mrow[2][2] = {{-1e30f, -1e30f}, {-1e30f, -1e30f}};
    float lrow[2][2] = {{0.f, 0.f}, {0.f, 0.f}};

    const int nkt = 2 * qt + 2;

    auto prefetch = [&](int kt, int st) {
        const int k0 = kt * 64;
#pragma unroll
        for (int i = 0; i < 4; i++) {
            const int idx = t + 128 * i;          // 0..511
            const int r = idx >> 3, c = (idx & 7) * 8;
            cp16(smem_u32(&sk[st][r * 72 + c]), kb + (size_t)(k0 + r) * HDD + c);
            cp16(smem_u32(&sv[st][r * 72 + c]), vb + (size_t)r * SS + k0 + c);
        }
        cp_commit();
    };

    prefetch(0, 0);

    for (int kt = 0; kt < nkt; kt++) {
        const int k0 = kt * 64;
        const int st = kt & 1;
        if (kt + 1 < nkt) { prefetch(kt + 1, st ^ 1); cp_wait1(); }
        else              { cp_wait0(); }
        __syncthreads();

        float sacc[2][8][4];
#pragma unroll
        for (int i = 0; i < 2; i++)
#pragma unroll
            for (int j = 0; j < 8; j++)
#pragma unroll
                for (int c = 0; c < 4; c++) sacc[i][j][c] = 0.f;

#pragma unroll
        for (int kc = 0; kc < 4; kc++)
#pragma unroll
            for (int nt = 0; nt < 8; nt++) {
                const __half* kr = &sk[st][(8 * nt + g) * 72 + kc * 16];
                const uint32_t b0 = *(const uint32_t*)(kr + 2 * tig);
                const uint32_t b1 = *(const uint32_t*)(kr + 8 + 2 * tig);
                mma16816h(sacc[0][nt], qf[kc][0], b0, b1);
                mma16816h(sacc[1][nt], qf[kc][1], b0, b1);
            }

#pragma unroll
        for (int mt = 0; mt < 2; mt++)
#pragma unroll
            for (int hf = 0; hf < 2; hf++) {
                const int rowg = q0 + wm + 16 * mt + g + 8 * hf;
                const float* arow = ab + (size_t)rowg * SS + k0;
                float mx = -1e30f;
#pragma unroll
                for (int nt = 0; nt < 8; nt++) {
                    const int col = k0 + 8 * nt + 2 * tig;
                    const float2 al2 = *(const float2*)(arow + 8 * nt + 2 * tig);
                    float s0 = fmaf(sacc[mt][nt][2 * hf + 0], 0.125f, al2.x);
                    float s1 = fmaf(sacc[mt][nt][2 * hf + 1], 0.125f, al2.y);
                    if (col > rowg)     s0 = -1e30f;
                    if (col + 1 > rowg) s1 = -1e30f;
                    sacc[mt][nt][2 * hf + 0] = s0;
                    sacc[mt][nt][2 * hf + 1] = s1;
                    mx = fmaxf(mx, fmaxf(s0, s1));
                }
                mx = fmaxf(mx, __shfl_xor_sync(0xffffffffu, mx, 1));
                mx = fmaxf(mx, __shfl_xor_sync(0xffffffffu, mx, 2));
                const float mn = fmaxf(mrow[mt][hf], mx);
                const float corr = __expf(mrow[mt][hf] - mn);
                mrow[mt][hf] = mn;
                lrow[mt][hf] *= corr;
#pragma unroll
                for (int nt = 0; nt < 8; nt++) {
                    o[mt][nt][2 * hf + 0] *= corr;
                    o[mt][nt][2 * hf + 1] *= corr;
                }
                float ls = 0.f;
#pragma unroll
                for (int nt = 0; nt < 8; nt++) {
                    const float p0 = __expf(sacc[mt][nt][2 * hf + 0] - mn);
                    const float p1 = __expf(sacc[mt][nt][2 * hf + 1] - mn);
                    sacc[mt][nt][2 * hf + 0] = p0;
                    sacc[mt][nt][2 * hf + 1] = p1;
                    ls += p0 + p1;
                }
                ls += __shfl_xor_sync(0xffffffffu, ls, 1);
                ls += __shfl_xor_sync(0xffffffffu, ls, 2);
                lrow[mt][hf] += ls;
            }

#pragma unroll
        for (int kc = 0; kc < 4; kc++) {
            uint32_t ap[2][4];
#pragma unroll
            for (int mt = 0; mt < 2; mt++)
#pragma unroll
                for (int q2 = 0; q2 < 2; q2++) {
                    const float* pp = sacc[mt][2 * kc + q2];
                    ap[mt][2 * q2 + 0] = pack_f16(pp[0], pp[1]);
                    ap[mt][2 * q2 + 1] = pack_f16(pp[2], pp[3]);
                }
#pragma unroll
            for (int nt = 0; nt < 8; nt++) {
                const __half* vr = &sv[st][(8 * nt + g) * 72 + kc * 16];
                const uint32_t b0 = *(const uint32_t*)(vr + 2 * tig);
                const uint32_t b1 = *(const uint32_t*)(vr + 8 + 2 * tig);
                mma16816h(o[0][nt], ap[0], b0, b1);
                mma16816h(o[1][nt], ap[1], b0, b1);
            }
        }
        __syncthreads();
    }

#pragma unroll
    for (int mt = 0; mt < 2; mt++)
#pragma unroll
        for (int hf = 0; hf < 2; hf++) {
            const float inv = 1.f / lrow[mt][hf];
            const int rowg = b * SS + q0 + wm + 16 * mt + g + 8 * hf;
#pragma unroll
            for (int nt = 0; nt < 8; nt++) {
                const int col = h * HDD + 8 * nt + 2 * tig;
                *(uint32_t*)(O + toff(rowg, col, DD / 32)) =
                    pack_f16(o[mt][nt][2 * hf + 0] * inv,
                             o[mt][nt][2 * hf + 1] * inv);
            }
        }
}

// ---------------------------------------------------------------------------
// LayerNorm; SPLIT emits tiled fp16
// ---------------------------------------------------------------------------
template <bool SPLIT>
__global__ void __launch_bounds__(256) ln_kernel(
    const float* __restrict__ in, const float* __restrict__ gw,
    const float* __restrict__ bw, float* __restrict__ out,
    __half* __restrict__ oh)
{
    const int row = blockIdx.x;
    const int t   = threadIdx.x;
    const float* p = in + (size_t)row * DD;

    const float v0 = p[t], v1 = p[t + 256], v2 = p[t + 512];
    float s  = v0 + v1 + v2;
    float sq = fmaf(v0, v0, fmaf(v1, v1, v2 * v2));

#pragma unroll
    for (int off = 16; off; off >>= 1) {
        s  += __shfl_down_sync(0xffffffffu, s, off);
        sq += __shfl_down_sync(0xffffffffu, sq, off);
    }
    __shared__ float rs[8], rq[8];
    __shared__ float mean_s, inv_s;
    const int w = t >> 5, lane = t & 31;
    if (lane == 0) { rs[w] = s; rq[w] = sq; }
    __syncthreads();
    if (t == 0) {
        float S = 0.f, Q = 0.f;
#pragma unroll
        for (int i = 0; i < 8; i++) { S += rs[i]; Q += rq[i]; }
        const float mean = S * (1.f / 768.f);
        const float var  = Q * (1.f / 768.f) - mean * mean;
        mean_s = mean;
        inv_s  = rsqrtf(var + 1e-5f);
    }
    __syncthreads();
    const float mean = mean_s, inv = inv_s;
    float* po = out + (size_t)row * DD;
#pragma unroll
    for (int j = 0; j < 3; j++) {
        const int  c = t + 256 * j;
        const float vj = (j == 0) ? v0 : (j == 1) ? v1 : v2;
        const float r = fmaf((vj - mean) * inv, gw[c], bw[c]);
        po[c] = r;
        if (SPLIT) oh[toff(row, c, DD / 32)] = __float2half_rn(r);
    }
}

// ---------------------------------------------------------------------------
// Launcher
// ---------------------------------------------------------------------------
extern "C" void kernel_launch(void* const* d_in, const int* in_sizes, int n_in,
                              void* d_out, int out_size)
{
    (void)in_sizes; (void)n_in; (void)out_size;
    const float* x     = (const float*)d_in[0];
    const float* alibi = (const float*)d_in[1];
    const float* Wq = (const float*)d_in[2];  const float* bq = (const float*)d_in[3];
    const float* Wk = (const float*)d_in[4];  const float* bk = (const float*)d_in[5];
    const float* Wv = (const float*)d_in[6];  const float* bv = (const float*)d_in[7];
    const float* Wo = (const float*)d_in[8];  const float* bo = (const float*)d_in[9];
    const float* W1 = (const float*)d_in[10]; const float* b1 = (const float*)d_in[11];
    const float* W2 = (const float*)d_in[12]; const float* b2 = (const float*)d_in[13];
    const float* g1w = (const float*)d_in[14]; const float* be1 = (const float*)d_in[15];
    const float* g2w = (const float*)d_in[16]; const float* be2 = (const float*)d_in[17];
    float* out = (float*)d_out;

    float *r1, *y, *z;
    cudaGetSymbolAddress((void**)&r1, g_res1);
    cudaGetSymbolAddress((void**)&y,  g_y);
    cudaGetSymbolAddress((void**)&z,  g_z);

    __half *xh, *ath, *yh, *h1h, *qh, *kh, *vh, *vt;
    __half *wq, *wk, *wv, *wo, *w1, *w2;
    cudaGetSymbolAddress((void**)&xh,  g_xh);
    cudaGetSymbolAddress((void**)&ath, g_ath);
    cudaGetSymbolAddress((void**)&yh,  g_yh);
    cudaGetSymbolAddress((void**)&h1h, g_h1h);
    cudaGetSymbolAddress((void**)&qh,  g_qh);
    cudaGetSymbolAddress((void**)&kh,  g_kh);
    cudaGetSymbolAddress((void**)&vh,  g_vh);
    cudaGetSymbolAddress((void**)&vt,  g_vt);
    cudaGetSymbolAddress((void**)&wq, g_wqT);
    cudaGetSymbolAddress((void**)&wk, g_wkT);
    cudaGetSymbolAddress((void**)&wv, g_wvT);
    cudaGetSymbolAddress((void**)&wo, g_woT);
    cudaGetSymbolAddress((void**)&w1, g_w1T);
    cudaGetSymbolAddress((void**)&w2, g_w2T);

    cudaFuncSetAttribute(gemm_h<M_QKV>, cudaFuncAttributeMaxDynamicSharedMemorySize, GEMM_SMEM);
    cudaFuncSetAttribute(gemm_h<M_WO>,  cudaFuncAttributeMaxDynamicSharedMemorySize, GEMM_SMEM);
    cudaFuncSetAttribute(gemm_h<M_FF1>, cudaFuncAttributeMaxDynamicSharedMemorySize, GEMM_SMEM);
    cudaFuncSetAttribute(gemm_h<M_FF2>, cudaFuncAttributeMaxDynamicSharedMemorySize, GEMM_SMEM);

    const dim3 tb(32, 8);

    Qkv3 qkv;
    qkv.p[0] = {wq, bq, qh};
    qkv.p[1] = {wk, bk, kh};
    qkv.p[2] = {wv, bv, vh};
    Qkv3 dummy = qkv;

    T4 t4;
    t4.W[0] = Wq; t4.T[0] = wq;
    t4.W[1] = Wk; t4.T[1] = wk;
    t4.W[2] = Wv; t4.T[2] = wv;
    t4.W[3] = Wo; t4.T[3] = wo;

    // prep (fused 4-way transpose; launches 1-4)
    convert_h<<<3072, 256>>>(x, xh);
    transpose4_h<<<dim3(24, 24, 4), tb>>>(t4);
    transpose_h<<<dim3(96, 24), tb>>>(W1, w1, DD, DFF);
    transpose_h<<<dim3(24, 96), tb>>>(W2, w2, DFF, DD);

    // fused QKV projections (proven 128x128 tiles)
    gemm_h<M_QKV><<<dim3(6, 32, 3), 256, GEMM_SMEM>>>(
        xh, nullptr, nullptr, nullptr, nullptr, nullptr,
        qkv, NROW, DD, DD);

    vtrans_h<<<dim3(32, 24), 256>>>(vh, vt);

    attn_tc<<<dim3(16, 12, 2), 128>>>(alibi, qh, kh, vt, ath);

    gemm_h<M_WO><<<dim3(6, 32), 256, GEMM_SMEM>>>(
        ath, wo, bo, x, r1, nullptr, dummy, NROW, DD, DD);
    ln_kernel<true><<<NROW, 256>>>(r1, g1w, be1, y, yh);

    gemm_h<M_FF1><<<dim3(24, 32), 256, GEMM_SMEM>>>(
        yh, w1, b1, nullptr, nullptr, h1h, dummy, NROW, DFF, DD);
    gemm_h<M_FF2><<<dim3(6, 32), 256, GEMM_SMEM>>>(
        h1h, w2, b2, y, z, nullptr, dummy, NROW, DD, DFF);
    ln_kernel<false><<<NROW, 256>>>(z, g2w, be2, out, nullptr);
}

// round 14
// speedup vs baseline: 1.0357x; 1.0357x over previous
#include <cuda_runtime.h>
#include <cuda_fp16.h>
#include <cstdint>
#include <cstddef>

// Problem constants
#define BB    2
#define SS    2048
#define DD    768
#define HH    12
#define HDD   64
#define DFF   3072
#define NROW  4096            // B*S

// GEMM tiling: 128x128 CTA tile, K chunks of 32, tiled global layout.
#define CH     32
#define PADC   40
#define TILE_HW 5120
#define TILE_B  10240
#define G_STAGE_B (2 * TILE_B)             // A + B (single-pass fp16)
#define GEMM_SMEM (3 * G_STAGE_B + 64)     // 3 stages + mbarriers

// attention smem: sk/sv 2x(64x72 half) + alibi 2x(128x68 float)
#define ATTN_SMEM (36864 + 69632)          // 106496 bytes

#define TSZ(R, K) ((size_t)(R) * (K) / 32 * 40)

// ---------------------------------------------------------------------------
// Scratch (device globals)
// ---------------------------------------------------------------------------
__device__ float g_res1[NROW * DD];
__device__ float g_y[NROW * DD];
__device__ float g_z[NROW * DD];

// tiled fp16 activations
__device__ __half g_xh[TSZ(NROW, DD)];
__device__ __half g_ath[TSZ(NROW, DD)];
__device__ __half g_yh[TSZ(NROW, DD)];
__device__ __half g_h1h[TSZ(NROW, DFF)];

// head-major fp16 q/k/v (linear) + per-head transposed V
__device__ __half g_qh[BB*HH*SS*HDD];
__device__ __half g_kh[BB*HH*SS*HDD];
__device__ __half g_vh[BB*HH*SS*HDD];
__device__ __half g_vt[BB*HH*SS*HDD];     // [bh][hd][s]

// tiled fp16 transposed weights [N, K]
__device__ __half g_wqT[TSZ(DD, DD)];
__device__ __half g_wkT[TSZ(DD, DD)];
__device__ __half g_wvT[TSZ(DD, DD)];
__device__ __half g_woT[TSZ(DD, DD)];
__device__ __half g_w1T[TSZ(DFF, DD)];
__device__ __half g_w2T[TSZ(DD, DFF)];

// ---------------------------------------------------------------------------
// helpers
// ---------------------------------------------------------------------------
__device__ __forceinline__ uint32_t smem_u32(const void* p) {
    uint32_t a;
    asm("{ .reg .u64 t; cvta.to.shared.u64 t, %1; cvt.u32.u64 %0, t; }"
        : "=r"(a) : "l"(p));
    return a;
}
__device__ __forceinline__ void mma16816h(float* d, const uint32_t* a,
                                          uint32_t b0, uint32_t b1) {
    asm volatile(
        "mma.sync.aligned.m16n8k16.row.col.f32.f16.f16.f32 "
        "{%0,%1,%2,%3}, {%4,%5,%6,%7}, {%8,%9}, {%0,%1,%2,%3};"
        : "+f"(d[0]), "+f"(d[1]), "+f"(d[2]), "+f"(d[3])
        : "r"(a[0]), "r"(a[1]), "r"(a[2]), "r"(a[3]), "r"(b0), "r"(b1));
}
__device__ __forceinline__ uint32_t pack_f16(float lo, float hi) {
    uint32_t r;
    asm("cvt.rn.f16x2.f32 %0, %1, %2;" : "=r"(r) : "f"(hi), "f"(lo));
    return r;
}
__device__ __forceinline__ void ldmx4(uint32_t* r, uint32_t addr) {
    asm volatile("ldmatrix.sync.aligned.m8n8.x4.shared.b16 {%0,%1,%2,%3}, [%4];"
                 : "=r"(r[0]), "=r"(r[1]), "=r"(r[2]), "=r"(r[3]) : "r"(addr));
}
__device__ __forceinline__ void mbar_init(uint32_t mbar, uint32_t cnt) {
    asm volatile("mbarrier.init.shared.b64 [%0], %1;" :: "r"(mbar), "r"(cnt) : "memory");
}
__device__ __forceinline__ void mbar_wait(uint32_t mbar, uint32_t parity) {
    asm volatile(
        "{\n\t.reg .pred P;\n\t"
        "WL_%=:\n\t"
        "mbarrier.try_wait.parity.acquire.cta.shared::cta.b64 P, [%0], %1, 0x989680;\n\t"
        "@P bra.uni WD_%=;\n\t"
        "bra.uni WL_%=;\n\t"
        "WD_%=:\n\t}"
        :: "r"(mbar), "r"(parity) : "memory");
}
__device__ __forceinline__ void mbar_expect_tx(uint32_t mbar, uint32_t bytes) {
    asm volatile("mbarrier.arrive.expect_tx.shared.b64 _, [%0], %1;"
                 :: "r"(mbar), "r"(bytes) : "memory");
}
__device__ __forceinline__ void bulkcp(uint32_t dst, const void* src,
                                       uint32_t bytes, uint32_t mbar) {
    asm volatile(
        "cp.async.bulk.shared::cta.global.mbarrier::complete_tx::bytes "
        "[%0], [%1], %2, [%3];"
        :: "r"(dst), "l"(src), "r"(bytes), "r"(mbar) : "memory");
}
__device__ __forceinline__ void cp16(uint32_t dst, const void* src) {
    asm volatile("cp.async.cg.shared.global [%0], [%1], 16;"
                 :: "r"(dst), "l"(src));
}
__device__ __forceinline__ void cp_commit() { asm volatile("cp.async.commit_group;"); }
__device__ __forceinline__ void cp_wait0()  { asm volatile("cp.async.wait_group 0;"); }
__device__ __forceinline__ void cp_wait1()  { asm volatile("cp.async.wait_group 1;"); }

__device__ __forceinline__ size_t toff(int row, int col, int kcn) {
    return (size_t)((row >> 7) * kcn + (col >> 5)) * TILE_HW +
           (row & 127) * PADC + (col & 31);
}

// ---------------------------------------------------------------------------
// fp32 [4096,768] -> tiled fp16
// ---------------------------------------------------------------------------
__global__ void __launch_bounds__(256) convert_h(
    const float* __restrict__ in, __half* __restrict__ oh)
{
    const int i = blockIdx.x * 256 + threadIdx.x;
    const int e = 4 * i;
    const int row = e / DD, col = e - row * DD;
    float4 v = ((const float4*)in)[i];
    const size_t o = toff(row, col, DD / 32);
    *(uint2*)(oh + o) = make_uint2(pack_f16(v.x, v.y), pack_f16(v.z, v.w));
}

// ---------------------------------------------------------------------------
// Fused 4x: W[768,768] fp32 -> tiled Wt[768,768] fp16 (blockIdx.z selects)
// ---------------------------------------------------------------------------
struct T4 { const float* W[4]; __half* T[4]; };

__global__ void __launch_bounds__(256) transpose4_h(T4 p)
{
    __shared__ float tile[32][33];
    const float* W = p.W[blockIdx.z];
    __half* T = p.T[blockIdx.z];
    const int k0 = blockIdx.y * 32, n0 = blockIdx.x * 32;
    const int tx = threadIdx.x, ty = threadIdx.y;   // (32, 8)
#pragma unroll
    for (int i = 0; i < 4; i++)
        tile[ty + 8 * i][tx] = W[(size_t)(k0 + ty + 8 * i) * DD + n0 + tx];
    __syncthreads();
#pragma unroll
    for (int i = 0; i < 4; i++)
        T[toff(n0 + ty + 8 * i, k0 + tx, DD >> 5)] =
            __float2half_rn(tile[tx][ty + 8 * i]);
}

// generic single transpose (W1 / W2)
__global__ void __launch_bounds__(256) transpose_h(
    const float* __restrict__ W, __half* __restrict__ T, int K, int N)
{
    __shared__ float tile[32][33];
    const int k0 = blockIdx.y * 32, n0 = blockIdx.x * 32;
    const int tx = threadIdx.x, ty = threadIdx.y;
#pragma unroll
    for (int i = 0; i < 4; i++)
        tile[ty + 8 * i][tx] = W[(size_t)(k0 + ty + 8 * i) * N + n0 + tx];
    __syncthreads();
    const int kcn = K >> 5;
#pragma unroll
    for (int i = 0; i < 4; i++)
        T[toff(n0 + ty + 8 * i, k0 + tx, kcn)] =
            __float2half_rn(tile[tx][ty + 8 * i]);
}

// ---------------------------------------------------------------------------
// per-head V transpose: [s, hd] -> [hd, s] (fp16, linear)
// ---------------------------------------------------------------------------
__global__ void __launch_bounds__(256) vtrans_h(
    const __half* __restrict__ in, __half* __restrict__ out)
{
    __shared__ uint16_t sm[64][72];
    const int s0 = blockIdx.x * 64;
    const size_t bh = blockIdx.y;
    const uint16_t* src = (const uint16_t*)(in + bh * SS * HDD);
    uint16_t* dst = (uint16_t*)(out + bh * (size_t)HDD * SS);
    const int t = threadIdx.x;
    const int r = t >> 2, cq = (t & 3) * 16;
    *(uint4*)(&sm[r][cq])     = *(const uint4*)(src + (size_t)(s0 + r) * HDD + cq);
    *(uint4*)(&sm[r][cq + 8]) = *(const uint4*)(src + (size_t)(s0 + r) * HDD + cq + 8);
    __syncthreads();
    uint32_t w[8];
#pragma unroll
    for (int j = 0; j < 8; j++)
        w[j] = ((uint32_t)sm[cq + 2 * j + 1][r] << 16) | sm[cq + 2 * j][r];
#pragma unroll
    for (int j = 0; j < 4; j++)
        *(uint2*)(dst + (size_t)r * SS + s0 + cq + 4 * j) =
            make_uint2(w[2 * j], w[2 * j + 1]);
}

// ---------------------------------------------------------------------------
// fp16 1-pass GEMM (R10/R13 proven): 128x128 tile, 8 warps 4(M)x2(N),
// 3-stage bulk-DMA pipeline.
// ---------------------------------------------------------------------------
#define M_QKV 0
#define M_WO  1
#define M_FF1 2
#define M_FF2 3

struct PtrQ {
    const __half* b;
    const float* bias;
    __half* c;            // fp16 linear head-major
};
struct Qkv3 { PtrQ p[3]; };

template <int MODE>
__global__ void __launch_bounds__(256) gemm_h(
    const __half* __restrict__ A, const __half* __restrict__ B_,
    const float* __restrict__ bias_, const float* __restrict__ res,
    float* __restrict__ Cf, __half* __restrict__ Ch_,
    Qkv3 qkv, int M, int N, int K)
{
    extern __shared__ char smem[];
    const uint32_t sb = smem_u32(smem);
    const uint32_t mbb = sb + 3 * G_STAGE_B;

    const int t    = threadIdx.x;
    const int lane = t & 31, wid = t >> 5;
    const int wm   = (wid & 3) * 32;
    const int wn   = (wid >> 2) * 64;
    const int bm   = blockIdx.y * 128, bn = blockIdx.x * 128;
    const int g    = lane >> 2, tig = lane & 3;

    const __half* B;
    const float* bias;
    __half* Ch = Ch_;
    if (MODE == M_QKV) {
        const PtrQ& p = qkv.p[blockIdx.z];
        B = p.b; bias = p.bias; Ch = p.c;
    } else {
        B = B_; bias = bias_;
    }

    if (t == 0) { mbar_init(mbb, 1); mbar_init(mbb + 8, 1); mbar_init(mbb + 16, 1); }
    __syncthreads();

    float acc[2][8][4];
#pragma unroll
    for (int i = 0; i < 2; i++)
#pragma unroll
        for (int j = 0; j < 8; j++)
#pragma unroll
            for (int c = 0; c < 4; c++) acc[i][j][c] = 0.f;

    const int KCN = K >> 5;
    const int arb = bm >> 7, brb = bn >> 7;

    auto issue = [&](int c, int stage) {
        if (t == 0) {
            const uint32_t mbar = mbb + stage * 8;
            mbar_expect_tx(mbar, G_STAGE_B);
            const uint32_t d = sb + stage * G_STAGE_B;
            bulkcp(d,          A + ((size_t)arb * KCN + c) * TILE_HW, TILE_B, mbar);
            bulkcp(d + TILE_B, B + ((size_t)brb * KCN + c) * TILE_HW, TILE_B, mbar);
        }
    };

    uint32_t ph[3] = {0, 0, 0};
    issue(0, 0);
    if (KCN > 1) issue(1, 1);

    const uint32_t lrow = (uint32_t)(lane & 15);
    const uint32_t lcol = (uint32_t)((lane >> 4) * 8);

    for (int c = 0; c < KCN; c++) {
        if (c + 2 < KCN) issue(c + 2, (c + 2) % 3);
        const int st = c % 3;
        mbar_wait(mbb + st * 8, ph[st]);
        ph[st] ^= 1;

        const uint32_t sA = sb + st * G_STAGE_B;
        const uint32_t sB = sA + TILE_B;

#pragma unroll
        for (int kk = 0; kk < CH; kk += 16) {
            uint32_t a[2][4];
            ldmx4(a[0], sA + ((wm + lrow) * PADC + kk + lcol) * 2);
            ldmx4(a[1], sA + ((wm + 16 + lrow) * PADC + kk + lcol) * 2);
#pragma unroll
            for (int p = 0; p < 4; p++) {
                uint32_t bf[4];
                ldmx4(bf, sB + ((wn + 16 * p + lrow) * PADC + kk + lcol) * 2);
#pragma unroll
                for (int q = 0; q < 2; q++) {
                    const int nt = 2 * p + q;
                    mma16816h(acc[0][nt], a[0], bf[q], bf[q + 2]);
                    mma16816h(acc[1][nt], a[1], bf[q], bf[q + 2]);
                }
            }
        }
        __syncthreads();
    }

    const int okcn = N >> 5;
#pragma unroll
    for (int mt = 0; mt < 2; mt++) {
#pragma unroll
        for (int nt = 0; nt < 8; nt++) {
#pragma unroll
            for (int half = 0; half < 2; half++) {
                const int grow = bm + wm + mt * 16 + g + half * 8;
                const int gcol = bn + wn + nt * 8 + 2 * tig;
                float v0 = acc[mt][nt][half * 2 + 0] + bias[gcol];
                float v1 = acc[mt][nt][half * 2 + 1] + bias[gcol + 1];
                if (MODE == M_QKV) {
                    const int b_ = grow >> 11, s_ = grow & 2047;
                    const int h_ = gcol >> 6,  hd = gcol & 63;
                    *(uint32_t*)(Ch + (((size_t)(b_ * HH + h_) * SS) + s_) * HDD + hd) =
                        pack_f16(v0, v1);
                } else if (MODE == M_FF1) {
                    v0 = fmaxf(v0, 0.f);
                    v1 = fmaxf(v1, 0.f);
                    *(uint32_t*)(Ch + toff(grow, gcol, okcn)) = pack_f16(v0, v1);
                } else {
                    const size_t o = (size_t)grow * N + gcol;
                    v0 += res[o];
                    v1 += res[o + 1];
                    *(float2*)(Cf + o) = make_float2(v0, v1);
                }
            }
        }
    }
}

// ---------------------------------------------------------------------------
// fp16 1-pass tensor-core flash attention.
// NEW: alibi tile prefetched through the same cp.async double buffer as K/V
// (dynamic smem: sk/sv 2x9216B each + alibi 2x34816B).
// ---------------------------------------------------------------------------
__global__ void __launch_bounds__(128) attn_tc(
    const float* __restrict__ alibi,
    const __half* __restrict__ Q, const __half* __restrict__ K,
    const __half* __restrict__ Vt, __half* __restrict__ O)
{
    extern __shared__ char smem[];
    __half* skb = (__half*)smem;                   // [2][64*72]
    __half* svb = (__half*)(smem + 18432);         // [2][64*72]
    float*  alb = (float*)(smem + 36864);          // [2][128*68]

    const int t = threadIdx.x, lane = t & 31, wid = t >> 5;
    const int g = lane >> 2, tig = lane & 3;
    const int qt = (int)(gridDim.x - 1) - (int)blockIdx.x;
    const int h = blockIdx.y, b = blockIdx.z;
    const int q0 = qt * 128, wm = wid * 32;
    const size_t bh = (size_t)(b * HH + h);

    const __half* qb = Q + (bh * SS + q0) * HDD;
    const __half* kb = K + bh * SS * HDD;
    const __half* vb = Vt + bh * (size_t)HDD * SS;
    const float* ab = alibi + (size_t)h * SS * SS;

    uint32_t qf[4][2][4];
#pragma unroll
    for (int kc = 0; kc < 4; kc++)
#pragma unroll
        for (int mt = 0; mt < 2; mt++) {
            const int row = wm + mt * 16 + g;
            qf[kc][mt][0] = *(const uint32_t*)(qb + (size_t)row * HDD + kc * 16 + 2 * tig);
            qf[kc][mt][1] = *(const uint32_t*)(qb + (size_t)(row + 8) * HDD + kc * 16 + 2 * tig);
            qf[kc][mt][2] = *(const uint32_t*)(qb + (size_t)row * HDD + kc * 16 + 8 + 2 * tig);
            qf[kc][mt][3] = *(const uint32_t*)(qb + (size_t)(row + 8) * HDD + kc * 16 + 8 + 2 * tig);
        }

    float o[2][8][4];
#pragma unroll
    for (int i = 0; i < 2; i++)
#pragma unroll
        for (int j = 0; j < 8; j++)
#pragma unroll
            for (int c = 0; c < 4; c++) o[i][j][c] = 0.f;
    float mrow[2][2] = {{-1e30f, -1e30f}, {-1e30f, -1e30f}};
    float lrow[2][2] = {{0.f, 0.f}, {0.f, 0.f}};

    const int nkt = 2 * qt + 2;

    auto prefetch = [&](int kt, int st) {
        const int k0 = kt * 64;
        __half* sk = skb + st * 4608;
        __half* sv = svb + st * 4608;
        float*  sa = alb + st * 8704;
#pragma unroll
        for (int i = 0; i < 4; i++) {
            const int idx = t + 128 * i;          // 0..511
            const int r = idx >> 3, c = (idx & 7) * 8;
            cp16(smem_u32(sk + r * 72 + c), kb + (size_t)(k0 + r) * HDD + c);
            cp16(smem_u32(sv + r * 72 + c), vb + (size_t)r * SS + k0 + c);
        }
#pragma unroll
        for (int i = 0; i < 16; i++) {
            const int idx = t + 128 * i;          // 0..2047 chunks of 16B
            const int r = idx >> 4, c4 = (idx & 15) * 4;
            cp16(smem_u32(sa + r * 68 + c4),
                 ab + (size_t)(q0 + r) * SS + k0 + c4);
        }
        cp_commit();
    };

    prefetch(0, 0);

    for (int kt = 0; kt < nkt; kt++) {
        const int k0 = kt * 64;
        const int st = kt & 1;
        if (kt + 1 < nkt) { prefetch(kt + 1, st ^ 1); cp_wait1(); }
        else              { cp_wait0(); }
        __syncthreads();

        const __half* sk = skb + st * 4608;
        const __half* sv = svb + st * 4608;
        const float*  sa = alb + st * 8704;

        float sacc[2][8][4];
#pragma unroll
        for (int i = 0; i < 2; i++)
#pragma unroll
            for (int j = 0; j < 8; j++)
#pragma unroll
                for (int c = 0; c < 4; c++) sacc[i][j][c] = 0.f;

#pragma unroll
        for (int kc = 0; kc < 4; kc++)
#pragma unroll
            for (int nt = 0; nt < 8; nt++) {
                const __half* kr = sk + (8 * nt + g) * 72 + kc * 16;
                const uint32_t b0 = *(const uint32_t*)(kr + 2 * tig);
                const uint32_t b1 = *(const uint32_t*)(kr + 8 + 2 * tig);
                mma16816h(sacc[0][nt], qf[kc][0], b0, b1);
                mma16816h(sacc[1][nt], qf[kc][1], b0, b1);
            }

#pragma unroll
        for (int mt = 0; mt < 2; mt++)
#pragma unroll
            for (int hf = 0; hf < 2; hf++) {
                const int lrowi = wm + 16 * mt + g + 8 * hf;   // 0..127
                const int rowg  = q0 + lrowi;
                const float* arow = sa + lrowi * 68;
                float mx = -1e30f;
#pragma unroll
                for (int nt = 0; nt < 8; nt++) {
                    const int col = k0 + 8 * nt + 2 * tig;
                    const float2 al2 = *(const float2*)(arow + 8 * nt + 2 * tig);
                    float s0 = fmaf(sacc[mt][nt][2 * hf + 0], 0.125f, al2.x);
                    float s1 = fmaf(sacc[mt][nt][2 * hf + 1], 0.125f, al2.y);
                    if (col > rowg)     s0 = -1e30f;
                    if (col + 1 > rowg) s1 = -1e30f;
                    sacc[mt][nt][2 * hf + 0] = s0;
                    sacc[mt][nt][2 * hf + 1] = s1;
                    mx = fmaxf(mx, fmaxf(s0, s1));
                }
                mx = fmaxf(mx, __shfl_xor_sync(0xffffffffu, mx, 1));
                mx = fmaxf(mx, __shfl_xor_sync(0xffffffffu, mx, 2));
                const float mn = fmaxf(mrow[mt][hf], mx);
                const float corr = __expf(mrow[mt][hf] - mn);
                mrow[mt][hf] = mn;
                lrow[mt][hf] *= corr;
#pragma unroll
                for (int nt = 0; nt < 8; nt++) {
                    o[mt][nt][2 * hf + 0] *= corr;
                    o[mt][nt][2 * hf + 1] *= corr;
                }
                float ls = 0.f;
#pragma unroll
                for (int nt = 0; nt < 8; nt++) {
                    const float p0 = __expf(sacc[mt][nt][2 * hf + 0] - mn);
                    const float p1 = __expf(sacc[mt][nt][2 * hf + 1] - mn);
                    sacc[mt][nt][2 * hf + 0] = p0;
                    sacc[mt][nt][2 * hf + 1] = p1;
                    ls += p0 + p1;
                }
                ls += __shfl_xor_sync(0xffffffffu, ls, 1);
                ls += __shfl_xor_sync(0xffffffffu, ls, 2);
                lrow[mt][hf] += ls;
            }

#pragma unroll
        for (int kc = 0; kc < 4; kc++) {
            uint32_t ap[2][4];
#pragma unroll
            for (int mt = 0; mt < 2; mt++)
#pragma unroll
                for (int q2 = 0; q2 < 2; q2++) {
                    const float* pp = sacc[mt][2 * kc + q2];
                    ap[mt][2 * q2 + 0] = pack_f16(pp[0], pp[1]);
                    ap[mt][2 * q2 + 1] = pack_f16(pp[2], pp[3]);
                }
#pragma unroll
            for (int nt = 0; nt < 8; nt++) {
                const __half* vr = sv + (8 * nt + g) * 72 + kc * 16;
                const uint32_t b0 = *(const uint32_t*)(vr + 2 * tig);
                const uint32_t b1 = *(const uint32_t*)(vr + 8 + 2 * tig);
                mma16816h(o[0][nt], ap[0], b0, b1);
                mma16816h(o[1][nt], ap[1], b0, b1);
            }
        }
        __syncthreads();
    }

#pragma unroll
    for (int mt = 0; mt < 2; mt++)
#pragma unroll
        for (int hf = 0; hf < 2; hf++) {
            const float inv = 1.f / lrow[mt][hf];
            const int rowg = b * SS + q0 + wm + 16 * mt + g + 8 * hf;
#pragma unroll
            for (int nt = 0; nt < 8; nt++) {
                const int col = h * HDD + 8 * nt + 2 * tig;
                *(uint32_t*)(O + toff(rowg, col, DD / 32)) =
                    pack_f16(o[mt][nt][2 * hf + 0] * inv,
                             o[mt][nt][2 * hf + 1] * inv);
            }
        }
}

// ---------------------------------------------------------------------------
// LayerNorm; SPLIT emits tiled fp16
// ---------------------------------------------------------------------------
template <bool SPLIT>
__global__ void __launch_bounds__(256) ln_kernel(
    const float* __restrict__ in, const float* __restrict__ gw,
    const float* __restrict__ bw, float* __restrict__ out,
    __half* __restrict__ oh)
{
    const int row = blockIdx.x;
    const int t   = threadIdx.x;
    const float* p = in + (size_t)row * DD;

    const float v0 = p[t], v1 = p[t + 256], v2 = p[t + 512];
    float s  = v0 + v1 + v2;
    float sq = fmaf(v0, v0, fmaf(v1, v1, v2 * v2));

#pragma unroll
    for (int off = 16; off; off >>= 1) {
        s  += __shfl_down_sync(0xffffffffu, s, off);
        sq += __shfl_down_sync(0xffffffffu, sq, off);
    }
    __shared__ float rs[8], rq[8];
    __shared__ float mean_s, inv_s;
    const int w = t >> 5, lane = t & 31;
    if (lane == 0) { rs[w] = s; rq[w] = sq; }
    __syncthreads();
    if (t == 0) {
        float S = 0.f, Q = 0.f;
#pragma unroll
        for (int i = 0; i < 8; i++) { S += rs[i]; Q += rq[i]; }
        const float mean = S * (1.f / 768.f);
        const float var  = Q * (1.f / 768.f) - mean * mean;
        mean_s = mean;
        inv_s  = rsqrtf(var + 1e-5f);
    }
    __syncthreads();
    const float mean = mean_s, inv = inv_s;
    float* po = out + (size_t)row * DD;
#pragma unroll
    for (int j = 0; j < 3; j++) {
        const int  c = t + 256 * j;
        const float vj = (j == 0) ? v0 : (j == 1) ? v1 : v2;
        const float r = fmaf((vj - mean) * inv, gw[c], bw[c]);
        po[c] = r;
        if (SPLIT) oh[toff(row, c, DD / 32)] = __float2half_rn(r);
    }
}

// ---------------------------------------------------------------------------
// Launcher
// ---------------------------------------------------------------------------
extern "C" void kernel_launch(void* const* d_in, const int* in_sizes, int n_in,
                              void* d_out, int out_size)
{
    (void)in_sizes; (void)n_in; (void)out_size;
    const float* x     = (const float*)d_in[0];
    const float* alibi = (const float*)d_in[1];
    const float* Wq = (const float*)d_in[2];  const float* bq = (const float*)d_in[3];
    const float* Wk = (const float*)d_in[4];  const float* bk = (const float*)d_in[5];
    const float* Wv = (const float*)d_in[6];  const float* bv = (const float*)d_in[7];
    const float* Wo = (const float*)d_in[8];  const float* bo = (const float*)d_in[9];
    const float* W1 = (const float*)d_in[10]; const float* b1 = (const float*)d_in[11];
    const float* W2 = (const float*)d_in[12]; const float* b2 = (const float*)d_in[13];
    const float* g1w = (const float*)d_in[14]; const float* be1 = (const float*)d_in[15];
    const float* g2w = (const float*)d_in[16]; const float* be2 = (const float*)d_in[17];
    float* out = (float*)d_out;

    float *r1, *y, *z;
    cudaGetSymbolAddress((void**)&r1, g_res1);
    cudaGetSymbolAddress((void**)&y,  g_y);
    cudaGetSymbolAddress((void**)&z,  g_z);

    __half *xh, *ath, *yh, *h1h, *qh, *kh, *vh, *vt;
    __half *wq, *wk, *wv, *wo, *w1, *w2;
    cudaGetSymbolAddress((void**)&xh,  g_xh);
    cudaGetSymbolAddress((void**)&ath, g_ath);
    cudaGetSymbolAddress((void**)&yh,  g_yh);
    cudaGetSymbolAddress((void**)&h1h, g_h1h);
    cudaGetSymbolAddress((void**)&qh,  g_qh);
    cudaGetSymbolAddress((void**)&kh,  g_kh);
    cudaGetSymbolAddress((void**)&vh,  g_vh);
    cudaGetSymbolAddress((void**)&vt,  g_vt);
    cudaGetSymbolAddress((void**)&wq, g_wqT);
    cudaGetSymbolAddress((void**)&wk, g_wkT);
    cudaGetSymbolAddress((void**)&wv, g_wvT);
    cudaGetSymbolAddress((void**)&wo, g_woT);
    cudaGetSymbolAddress((void**)&w1, g_w1T);
    cudaGetSymbolAddress((void**)&w2, g_w2T);

    cudaFuncSetAttribute(gemm_h<M_QKV>, cudaFuncAttributeMaxDynamicSharedMemorySize, GEMM_SMEM);
    cudaFuncSetAttribute(gemm_h<M_WO>,  cudaFuncAttributeMaxDynamicSharedMemorySize, GEMM_SMEM);
    cudaFuncSetAttribute(gemm_h<M_FF1>, cudaFuncAttributeMaxDynamicSharedMemorySize, GEMM_SMEM);
    cudaFuncSetAttribute(gemm_h<M_FF2>, cudaFuncAttributeMaxDynamicSharedMemorySize, GEMM_SMEM);
    cudaFuncSetAttribute(attn_tc, cudaFuncAttributeMaxDynamicSharedMemorySize, ATTN_SMEM);

    const dim3 tb(32, 8);

    Qkv3 qkv;
    qkv.p[0] = {wq, bq, qh};
    qkv.p[1] = {wk, bk, kh};
    qkv.p[2] = {wv, bv, vh};
    Qkv3 dummy = qkv;

    T4 t4;
    t4.W[0] = Wq; t4.T[0] = wq;
    t4.W[1] = Wk; t4.T[1] = wk;
    t4.W[2] = Wv; t4.T[2] = wv;
    t4.W[3] = Wo; t4.T[3] = wo;

    // prep
    convert_h<<<3072, 256>>>(x, xh);
    transpose4_h<<<dim3(24, 24, 4), tb>>>(t4);
    transpose_h<<<dim3(96, 24), tb>>>(W1, w1, DD, DFF);
    transpose_h<<<dim3(24, 96), tb>>>(W2, w2, DFF, DD);

    // fused QKV projections
    gemm_h<M_QKV><<<dim3(6, 32, 3), 256, GEMM_SMEM>>>(
        xh, nullptr, nullptr, nullptr, nullptr, nullptr,
        qkv, NROW, DD, DD);

    vtrans_h<<<dim3(32, 24), 256>>>(vh, vt);

    // attention with alibi prefetch pipeline
    attn_tc<<<dim3(16, 12, 2), 128, ATTN_SMEM>>>(alibi, qh, kh, vt, ath);

    gemm_h<M_WO><<<dim3(6, 32), 256, GEMM_SMEM>>>(
        ath, wo, bo, x, r1, nullptr, dummy, NROW, DD, DD);
    ln_kernel<true><<<NROW, 256>>>(r1, g1w, be1, y, yh);

    gemm_h<M_FF1><<<dim3(24, 32), 256, GEMM_SMEM>>>(
        yh, w1, b1, nullptr, nullptr, h1h, dummy, NROW, DFF, DD);
    gemm_h<M_FF2><<<dim3(6, 32), 256, GEMM_SMEM>>>(
        h1h, w2, b2, y, z, nullptr, dummy, NROW, DD, DFF);
    ln_kernel<false><<<NROW, 256>>>(z, g2w, be2, out, nullptr);
}

// round 15
// speedup vs baseline: 1.0517x; 1.0155x over previous
#include <cuda_runtime.h>
#include <cuda_fp16.h>
#include <cstdint>
#include <cstddef>

// Problem constants
#define BB    2
#define SS    2048
#define DD    768
#define HH    12
#define HDD   64
#define DFF   3072
#define NROW  4096            // B*S

// GEMM tiling: 128x128 CTA tile, K chunks of 32, tiled global layout.
#define CH     32
#define PADC   40
#define TILE_HW 5120
#define TILE_B  10240
#define G_STAGE_B (2 * TILE_B)             // A + B (single-pass fp16)
#define GEMM_SMEM (3 * G_STAGE_B + 64)     // 3 stages + mbarriers

// attention smem: sk/sv 2x(64x72 half) + alibi 2x(128x68 float)
#define ATTN_SMEM (36864 + 69632)          // 106496 bytes

// split-KV: qt >= 8 handled by 2 CTAs each
#define NSPLIT_U 384                       // 8 qt x 2 parts x 24 (b,h)

#define TSZ(R, K) ((size_t)(R) * (K) / 32 * 40)

// ---------------------------------------------------------------------------
// Scratch (device globals)
// ---------------------------------------------------------------------------
__device__ float g_res1[NROW * DD];
__device__ float g_y[NROW * DD];
__device__ float g_z[NROW * DD];

// split-KV partials: per split item u: o[128][64], m[128], l[128]
__device__ float g_po[NSPLIT_U * 128 * 64];
__device__ float g_pm[NSPLIT_U * 128];
__device__ float g_pl[NSPLIT_U * 128];

// tiled fp16 activations
__device__ __half g_xh[TSZ(NROW, DD)];
__device__ __half g_ath[TSZ(NROW, DD)];
__device__ __half g_yh[TSZ(NROW, DD)];
__device__ __half g_h1h[TSZ(NROW, DFF)];

// head-major fp16 q/k/v (linear) + per-head transposed V
__device__ __half g_qh[BB*HH*SS*HDD];
__device__ __half g_kh[BB*HH*SS*HDD];
__device__ __half g_vh[BB*HH*SS*HDD];
__device__ __half g_vt[BB*HH*SS*HDD];     // [bh][hd][s]

// tiled fp16 transposed weights [N, K]
__device__ __half g_wqT[TSZ(DD, DD)];
__device__ __half g_wkT[TSZ(DD, DD)];
__device__ __half g_wvT[TSZ(DD, DD)];
__device__ __half g_woT[TSZ(DD, DD)];
__device__ __half g_w1T[TSZ(DFF, DD)];
__device__ __half g_w2T[TSZ(DD, DFF)];

// ---------------------------------------------------------------------------
// helpers
// ---------------------------------------------------------------------------
__device__ __forceinline__ uint32_t smem_u32(const void* p) {
    uint32_t a;
    asm("{ .reg .u64 t; cvta.to.shared.u64 t, %1; cvt.u32.u64 %0, t; }"
        : "=r"(a) : "l"(p));
    return a;
}
__device__ __forceinline__ void mma16816h(float* d, const uint32_t* a,
                                          uint32_t b0, uint32_t b1) {
    asm volatile(
        "mma.sync.aligned.m16n8k16.row.col.f32.f16.f16.f32 "
        "{%0,%1,%2,%3}, {%4,%5,%6,%7}, {%8,%9}, {%0,%1,%2,%3};"
        : "+f"(d[0]), "+f"(d[1]), "+f"(d[2]), "+f"(d[3])
        : "r"(a[0]), "r"(a[1]), "r"(a[2]), "r"(a[3]), "r"(b0), "r"(b1));
}
__device__ __forceinline__ uint32_t pack_f16(float lo, float hi) {
    uint32_t r;
    asm("cvt.rn.f16x2.f32 %0, %1, %2;" : "=r"(r) : "f"(hi), "f"(lo));
    return r;
}
__device__ __forceinline__ void ldmx4(uint32_t* r, uint32_t addr) {
    asm volatile("ldmatrix.sync.aligned.m8n8.x4.shared.b16 {%0,%1,%2,%3}, [%4];"
                 : "=r"(r[0]), "=r"(r[1]), "=r"(r[2]), "=r"(r[3]) : "r"(addr));
}
__device__ __forceinline__ void mbar_init(uint32_t mbar, uint32_t cnt) {
    asm volatile("mbarrier.init.shared.b64 [%0], %1;" :: "r"(mbar), "r"(cnt) : "memory");
}
__device__ __forceinline__ void mbar_wait(uint32_t mbar, uint32_t parity) {
    asm volatile(
        "{\n\t.reg .pred P;\n\t"
        "WL_%=:\n\t"
        "mbarrier.try_wait.parity.acquire.cta.shared::cta.b64 P, [%0], %1, 0x989680;\n\t"
        "@P bra.uni WD_%=;\n\t"
        "bra.uni WL_%=;\n\t"
        "WD_%=:\n\t}"
        :: "r"(mbar), "r"(parity) : "memory");
}
__device__ __forceinline__ void mbar_expect_tx(uint32_t mbar, uint32_t bytes) {
    asm volatile("mbarrier.arrive.expect_tx.shared.b64 _, [%0], %1;"
                 :: "r"(mbar), "r"(bytes) : "memory");
}
__device__ __forceinline__ void bulkcp(uint32_t dst, const void* src,
                                       uint32_t bytes, uint32_t mbar) {
    asm volatile(
        "cp.async.bulk.shared::cta.global.mbarrier::complete_tx::bytes "
        "[%0], [%1], %2, [%3];"
        :: "r"(dst), "l"(src), "r"(bytes), "r"(mbar) : "memory");
}
__device__ __forceinline__ void cp16(uint32_t dst, const void* src) {
    asm volatile("cp.async.cg.shared.global [%0], [%1], 16;"
                 :: "r"(dst), "l"(src));
}
__device__ __forceinline__ void cp_commit() { asm volatile("cp.async.commit_group;"); }
__device__ __forceinline__ void cp_wait0()  { asm volatile("cp.async.wait_group 0;"); }
__device__ __forceinline__ void cp_wait1()  { asm volatile("cp.async.wait_group 1;"); }

__device__ __forceinline__ size_t toff(int row, int col, int kcn) {
    return (size_t)((row >> 7) * kcn + (col >> 5)) * TILE_HW +
           (row & 127) * PADC + (col & 31);
}

// ---------------------------------------------------------------------------
// fp32 [4096,768] -> tiled fp16
// ---------------------------------------------------------------------------
__global__ void __launch_bounds__(256) convert_h(
    const float* __restrict__ in, __half* __restrict__ oh)
{
    const int i = blockIdx.x * 256 + threadIdx.x;
    const int e = 4 * i;
    const int row = e / DD, col = e - row * DD;
    float4 v = ((const float4*)in)[i];
    const size_t o = toff(row, col, DD / 32);
    *(uint2*)(oh + o) = make_uint2(pack_f16(v.x, v.y), pack_f16(v.z, v.w));
}

// ---------------------------------------------------------------------------
// Fused 4x: W[768,768] fp32 -> tiled Wt[768,768] fp16 (blockIdx.z selects)
// ---------------------------------------------------------------------------
struct T4 { const float* W[4]; __half* T[4]; };

__global__ void __launch_bounds__(256) transpose4_h(T4 p)
{
    __shared__ float tile[32][33];
    const float* W = p.W[blockIdx.z];
    __half* T = p.T[blockIdx.z];
    const int k0 = blockIdx.y * 32, n0 = blockIdx.x * 32;
    const int tx = threadIdx.x, ty = threadIdx.y;   // (32, 8)
#pragma unroll
    for (int i = 0; i < 4; i++)
        tile[ty + 8 * i][tx] = W[(size_t)(k0 + ty + 8 * i) * DD + n0 + tx];
    __syncthreads();
#pragma unroll
    for (int i = 0; i < 4; i++)
        T[toff(n0 + ty + 8 * i, k0 + tx, DD >> 5)] =
            __float2half_rn(tile[tx][ty + 8 * i]);
}

// generic single transpose (W1 / W2)
__global__ void __launch_bounds__(256) transpose_h(
    const float* __restrict__ W, __half* __restrict__ T, int K, int N)
{
    __shared__ float tile[32][33];
    const int k0 = blockIdx.y * 32, n0 = blockIdx.x * 32;
    const int tx = threadIdx.x, ty = threadIdx.y;
#pragma unroll
    for (int i = 0; i < 4; i++)
        tile[ty + 8 * i][tx] = W[(size_t)(k0 + ty + 8 * i) * N + n0 + tx];
    __syncthreads();
    const int kcn = K >> 5;
#pragma unroll
    for (int i = 0; i < 4; i++)
        T[toff(n0 + ty + 8 * i, k0 + tx, kcn)] =
            __float2half_rn(tile[tx][ty + 8 * i]);
}

// ---------------------------------------------------------------------------
// per-head V transpose: [s, hd] -> [hd, s] (fp16, linear)
// ---------------------------------------------------------------------------
__global__ void __launch_bounds__(256) vtrans_h(
    const __half* __restrict__ in, __half* __restrict__ out)
{
    __shared__ uint16_t sm[64][72];
    const int s0 = blockIdx.x * 64;
    const size_t bh = blockIdx.y;
    const uint16_t* src = (const uint16_t*)(in + bh * SS * HDD);
    uint16_t* dst = (uint16_t*)(out + bh * (size_t)HDD * SS);
    const int t = threadIdx.x;
    const int r = t >> 2, cq = (t & 3) * 16;
    *(uint4*)(&sm[r][cq])     = *(const uint4*)(src + (size_t)(s0 + r) * HDD + cq);
    *(uint4*)(&sm[r][cq + 8]) = *(const uint4*)(src + (size_t)(s0 + r) * HDD + cq + 8);
    __syncthreads();
    uint32_t w[8];
#pragma unroll
    for (int j = 0; j < 8; j++)
        w[j] = ((uint32_t)sm[cq + 2 * j + 1][r] << 16) | sm[cq + 2 * j][r];
#pragma unroll
    for (int j = 0; j < 4; j++)
        *(uint2*)(dst + (size_t)r * SS + s0 + cq + 4 * j) =
            make_uint2(w[2 * j], w[2 * j + 1]);
}

// ---------------------------------------------------------------------------
// fp16 1-pass GEMM (proven): 128x128 tile, 8 warps 4(M)x2(N),
// 3-stage bulk-DMA pipeline.
// ---------------------------------------------------------------------------
#define M_QKV 0
#define M_WO  1
#define M_FF1 2
#define M_FF2 3

struct PtrQ {
    const __half* b;
    const float* bias;
    __half* c;            // fp16 linear head-major
};
struct Qkv3 { PtrQ p[3]; };

template <int MODE>
__global__ void __launch_bounds__(256) gemm_h(
    const __half* __restrict__ A, const __half* __restrict__ B_,
    const float* __restrict__ bias_, const float* __restrict__ res,
    float* __restrict__ Cf, __half* __restrict__ Ch_,
    Qkv3 qkv, int M, int N, int K)
{
    extern __shared__ char smem[];
    const uint32_t sb = smem_u32(smem);
    const uint32_t mbb = sb + 3 * G_STAGE_B;

    const int t    = threadIdx.x;
    const int lane = t & 31, wid = t >> 5;
    const int wm   = (wid & 3) * 32;
    const int wn   = (wid >> 2) * 64;
    const int bm   = blockIdx.y * 128, bn = blockIdx.x * 128;
    const int g    = lane >> 2, tig = lane & 3;

    const __half* B;
    const float* bias;
    __half* Ch = Ch_;
    if (MODE == M_QKV) {
        const PtrQ& p = qkv.p[blockIdx.z];
        B = p.b; bias = p.bias; Ch = p.c;
    } else {
        B = B_; bias = bias_;
    }

    if (t == 0) { mbar_init(mbb, 1); mbar_init(mbb + 8, 1); mbar_init(mbb + 16, 1); }
    __syncthreads();

    float acc[2][8][4];
#pragma unroll
    for (int i = 0; i < 2; i++)
#pragma unroll
        for (int j = 0; j < 8; j++)
#pragma unroll
            for (int c = 0; c < 4; c++) acc[i][j][c] = 0.f;

    const int KCN = K >> 5;
    const int arb = bm >> 7, brb = bn >> 7;

    auto issue = [&](int c, int stage) {
        if (t == 0) {
            const uint32_t mbar = mbb + stage * 8;
            mbar_expect_tx(mbar, G_STAGE_B);
            const uint32_t d = sb + stage * G_STAGE_B;
            bulkcp(d,          A + ((size_t)arb * KCN + c) * TILE_HW, TILE_B, mbar);
            bulkcp(d + TILE_B, B + ((size_t)brb * KCN + c) * TILE_HW, TILE_B, mbar);
        }
    };

    uint32_t ph[3] = {0, 0, 0};
    issue(0, 0);
    if (KCN > 1) issue(1, 1);

    const uint32_t lrow = (uint32_t)(lane & 15);
    const uint32_t lcol = (uint32_t)((lane >> 4) * 8);

    for (int c = 0; c < KCN; c++) {
        if (c + 2 < KCN) issue(c + 2, (c + 2) % 3);
        const int st = c % 3;
        mbar_wait(mbb + st * 8, ph[st]);
        ph[st] ^= 1;

        const uint32_t sA = sb + st * G_STAGE_B;
        const uint32_t sB = sA + TILE_B;

#pragma unroll
        for (int kk = 0; kk < CH; kk += 16) {
            uint32_t a[2][4];
            ldmx4(a[0], sA + ((wm + lrow) * PADC + kk + lcol) * 2);
            ldmx4(a[1], sA + ((wm + 16 + lrow) * PADC + kk + lcol) * 2);
#pragma unroll
            for (int p = 0; p < 4; p++) {
                uint32_t bf[4];
                ldmx4(bf, sB + ((wn + 16 * p + lrow) * PADC + kk + lcol) * 2);
#pragma unroll
                for (int q = 0; q < 2; q++) {
                    const int nt = 2 * p + q;
                    mma16816h(acc[0][nt], a[0], bf[q], bf[q + 2]);
                    mma16816h(acc[1][nt], a[1], bf[q], bf[q + 2]);
                }
            }
        }
        __syncthreads();
    }

    const int okcn = N >> 5;
#pragma unroll
    for (int mt = 0; mt < 2; mt++) {
#pragma unroll
        for (int nt = 0; nt < 8; nt++) {
#pragma unroll
            for (int half = 0; half < 2; half++) {
                const int grow = bm + wm + mt * 16 + g + half * 8;
                const int gcol = bn + wn + nt * 8 + 2 * tig;
                float v0 = acc[mt][nt][half * 2 + 0] + bias[gcol];
                float v1 = acc[mt][nt][half * 2 + 1] + bias[gcol + 1];
                if (MODE == M_QKV) {
                    const int b_ = grow >> 11, s_ = grow & 2047;
                    const int h_ = gcol >> 6,  hd = gcol & 63;
                    *(uint32_t*)(Ch + (((size_t)(b_ * HH + h_) * SS) + s_) * HDD + hd) =
                        pack_f16(v0, v1);
                } else if (MODE == M_FF1) {
                    v0 = fmaxf(v0, 0.f);
                    v1 = fmaxf(v1, 0.f);
                    *(uint32_t*)(Ch + toff(grow, gcol, okcn)) = pack_f16(v0, v1);
                } else {
                    const size_t o = (size_t)grow * N + gcol;
                    v0 += res[o];
                    v1 += res[o + 1];
                    *(float2*)(Cf + o) = make_float2(v0, v1);
                }
            }
        }
    }
}

// ---------------------------------------------------------------------------
// fp16 flash attention with split-KV for qt >= 8.
// Work decode (bx in [0, 576)):
//   bx < 384:  split item u=bx: qt = 15 - u/48, part = (u/24)&1,
//              h = (u%24)%12, b = (u%24)/12. Key range half; writes fp32
//              partials (unnormalized o, m, l) to scratch at index u.
//   bx >= 384: non-split v=bx-384: qt = 7 - v/24, full range, direct fp16 out.
// ---------------------------------------------------------------------------
__global__ void __launch_bounds__(128) attn_tc(
    const float* __restrict__ alibi,
    const __half* __restrict__ Q, const __half* __restrict__ K,
    const __half* __restrict__ Vt, __half* __restrict__ O,
    float* __restrict__ Po, float* __restrict__ Pm, float* __restrict__ Pl)
{
    extern __shared__ char smem[];
    __half* skb = (__half*)smem;                   // [2][64*72]
    __half* svb = (__half*)(smem + 18432);         // [2][64*72]
    float*  alb = (float*)(smem + 36864);          // [2][128*68]

    const int t = threadIdx.x, lane = t & 31, wid = t >> 5;
    const int g = lane >> 2, tig = lane & 3;
    const int bx = blockIdx.x;

    int qt, h, b, kt0, kt1, u = -1;
    if (bx < NSPLIT_U) {
        u = bx;
        qt = 15 - u / 48;
        const int part = (u / 24) & 1;
        const int rem = u % 24;
        h = rem % 12;
        b = rem / 12;
        const int nkt = 2 * qt + 2;
        const int mid = nkt >> 1;
        kt0 = part ? mid : 0;
        kt1 = part ? nkt : mid;
    } else {
        const int v = bx - NSPLIT_U;
        qt = 7 - v / 24;
        const int rem = v % 24;
        h = rem % 12;
        b = rem / 12;
        kt0 = 0;
        kt1 = 2 * qt + 2;
    }

    const int q0 = qt * 128, wm = wid * 32;
    const size_t bh = (size_t)(b * HH + h);

    const __half* qb = Q + (bh * SS + q0) * HDD;
    const __half* kb = K + bh * SS * HDD;
    const __half* vb = Vt + bh * (size_t)HDD * SS;
    const float* ab = alibi + (size_t)h * SS * SS;

    uint32_t qf[4][2][4];
#pragma unroll
    for (int kc = 0; kc < 4; kc++)
#pragma unroll
        for (int mt = 0; mt < 2; mt++) {
            const int row = wm + mt * 16 + g;
            qf[kc][mt][0] = *(const uint32_t*)(qb + (size_t)row * HDD + kc * 16 + 2 * tig);
            qf[kc][mt][1] = *(const uint32_t*)(qb + (size_t)(row + 8) * HDD + kc * 16 + 2 * tig);
            qf[kc][mt][2] = *(const uint32_t*)(qb + (size_t)row * HDD + kc * 16 + 8 + 2 * tig);
            qf[kc][mt][3] = *(const uint32_t*)(qb + (size_t)(row + 8) * HDD + kc * 16 + 8 + 2 * tig);
        }

    float o[2][8][4];
#pragma unroll
    for (int i = 0; i < 2; i++)
#pragma unroll
        for (int j = 0; j < 8; j++)
#pragma unroll
            for (int c = 0; c < 4; c++) o[i][j][c] = 0.f;
    float mrow[2][2] = {{-1e30f, -1e30f}, {-1e30f, -1e30f}};
    float lrow[2][2] = {{0.f, 0.f}, {0.f, 0.f}};

    auto prefetch = [&](int kt, int st) {
        const int k0 = kt * 64;
        __half* sk = skb + st * 4608;
        __half* sv = svb + st * 4608;
        float*  sa = alb + st * 8704;
#pragma unroll
        for (int i = 0; i < 4; i++) {
            const int idx = t + 128 * i;
            const int r = idx >> 3, c = (idx & 7) * 8;
            cp16(smem_u32(sk + r * 72 + c), kb + (size_t)(k0 + r) * HDD + c);
            cp16(smem_u32(sv + r * 72 + c), vb + (size_t)r * SS + k0 + c);
        }
#pragma unroll
        for (int i = 0; i < 16; i++) {
            const int idx = t + 128 * i;
            const int r = idx >> 4, c4 = (idx & 15) * 4;
            cp16(smem_u32(sa + r * 68 + c4),
                 ab + (size_t)(q0 + r) * SS + k0 + c4);
        }
        cp_commit();
    };

    prefetch(kt0, 0);

    for (int kt = kt0; kt < kt1; kt++) {
        const int k0 = kt * 64;
        const int st = (kt - kt0) & 1;
        if (kt + 1 < kt1) { prefetch(kt + 1, st ^ 1); cp_wait1(); }
        else              { cp_wait0(); }
        __syncthreads();

        const __half* sk = skb + st * 4608;
        const __half* sv = svb + st * 4608;
        const float*  sa = alb + st * 8704;

        float sacc[2][8][4];
#pragma unroll
        for (int i = 0; i < 2; i++)
#pragma unroll
            for (int j = 0; j < 8; j++)
#pragma unroll
                for (int c = 0; c < 4; c++) sacc[i][j][c] = 0.f;

#pragma unroll
        for (int kc = 0; kc < 4; kc++)
#pragma unroll
            for (int nt = 0; nt < 8; nt++) {
                const __half* kr = sk + (8 * nt + g) * 72 + kc * 16;
                const uint32_t b0 = *(const uint32_t*)(kr + 2 * tig);
                const uint32_t b1 = *(const uint32_t*)(kr + 8 + 2 * tig);
                mma16816h(sacc[0][nt], qf[kc][0], b0, b1);
                mma16816h(sacc[1][nt], qf[kc][1], b0, b1);
            }

#pragma unroll
        for (int mt = 0; mt < 2; mt++)
#pragma unroll
            for (int hf = 0; hf < 2; hf++) {
                const int lrowi = wm + 16 * mt + g + 8 * hf;
                const int rowg  = q0 + lrowi;
                const float* arow = sa + lrowi * 68;
                float mx = -1e30f;
#pragma unroll
                for (int nt = 0; nt < 8; nt++) {
                    const int col = k0 + 8 * nt + 2 * tig;
                    const float2 al2 = *(const float2*)(arow + 8 * nt + 2 * tig);
                    float s0 = fmaf(sacc[mt][nt][2 * hf + 0], 0.125f, al2.x);
                    float s1 = fmaf(sacc[mt][nt][2 * hf + 1], 0.125f, al2.y);
                    if (col > rowg)     s0 = -1e30f;
                    if (col + 1 > rowg) s1 = -1e30f;
                    sacc[mt][nt][2 * hf + 0] = s0;
                    sacc[mt][nt][2 * hf + 1] = s1;
                    mx = fmaxf(mx, fmaxf(s0, s1));
                }
                mx = fmaxf(mx, __shfl_xor_sync(0xffffffffu, mx, 1));
                mx = fmaxf(mx, __shfl_xor_sync(0xffffffffu, mx, 2));
                const float mn = fmaxf(mrow[mt][hf], mx);
                const float corr = __expf(mrow[mt][hf] - mn);
                mrow[mt][hf] = mn;
                lrow[mt][hf] *= corr;
#pragma unroll
                for (int nt = 0; nt < 8; nt++) {
                    o[mt][nt][2 * hf + 0] *= corr;
                    o[mt][nt][2 * hf + 1] *= corr;
                }
                float ls = 0.f;
#pragma unroll
                for (int nt = 0; nt < 8; nt++) {
                    const float p0 = __expf(sacc[mt][nt][2 * hf + 0] - mn);
                    const float p1 = __expf(sacc[mt][nt][2 * hf + 1] - mn);
                    sacc[mt][nt][2 * hf + 0] = p0;
                    sacc[mt][nt][2 * hf + 1] = p1;
                    ls += p0 + p1;
                }
                ls += __shfl_xor_sync(0xffffffffu, ls, 1);
                ls += __shfl_xor_sync(0xffffffffu, ls, 2);
                lrow[mt][hf] += ls;
            }

#pragma unroll
        for (int kc = 0; kc < 4; kc++) {
            uint32_t ap[2][4];
#pragma unroll
            for (int mt = 0; mt < 2; mt++)
#pragma unroll
                for (int q2 = 0; q2 < 2; q2++) {
                    const float* pp = sacc[mt][2 * kc + q2];
                    ap[mt][2 * q2 + 0] = pack_f16(pp[0], pp[1]);
                    ap[mt][2 * q2 + 1] = pack_f16(pp[2], pp[3]);
                }
#pragma unroll
            for (int nt = 0; nt < 8; nt++) {
                const __half* vr = sv + (8 * nt + g) * 72 + kc * 16;
                const uint32_t b0 = *(const uint32_t*)(vr + 2 * tig);
                const uint32_t b1 = *(const uint32_t*)(vr + 8 + 2 * tig);
                mma16816h(o[0][nt], ap[0], b0, b1);
                mma16816h(o[1][nt], ap[1], b0, b1);
            }
        }
        __syncthreads();
    }

    if (u >= 0) {
        // split path: write fp32 partials (unnormalized)
        float* pob = Po + (size_t)u * 128 * 64;
#pragma unroll
        for (int mt = 0; mt < 2; mt++)
#pragma unroll
            for (int hf = 0; hf < 2; hf++) {
                const int lrowi = wm + 16 * mt + g + 8 * hf;
                if (tig == 0) {
                    Pm[u * 128 + lrowi] = mrow[mt][hf];
                    Pl[u * 128 + lrowi] = lrow[mt][hf];
                }
#pragma unroll
                for (int nt = 0; nt < 8; nt++)
                    *(float2*)(pob + lrowi * 64 + 8 * nt + 2 * tig) =
                        make_float2(o[mt][nt][2 * hf + 0],
                                    o[mt][nt][2 * hf + 1]);
            }
    } else {
        // direct path: normalize, write tiled fp16
#pragma unroll
        for (int mt = 0; mt < 2; mt++)
#pragma unroll
            for (int hf = 0; hf < 2; hf++) {
                const float inv = 1.f / lrow[mt][hf];
                const int rowg = b * SS + q0 + wm + 16 * mt + g + 8 * hf;
#pragma unroll
                for (int nt = 0; nt < 8; nt++) {
                    const int col = h * HDD + 8 * nt + 2 * tig;
                    *(uint32_t*)(O + toff(rowg, col, DD / 32)) =
                        pack_f16(o[mt][nt][2 * hf + 0] * inv,
                                 o[mt][nt][2 * hf + 1] * inv);
                }
            }
    }
}

// ---------------------------------------------------------------------------
// split-KV merge: combine the two halves of each qt>=8 item.
// grid = 192 (one per (qt,b,h)), block = 128 (one thread per q-row).
// ---------------------------------------------------------------------------
__global__ void __launch_bounds__(128) attn_merge(
    const float* __restrict__ Po, const float* __restrict__ Pm,
    const float* __restrict__ Pl, __half* __restrict__ O)
{
    const int v = blockIdx.x;                // 0..191
    const int qt = 15 - v / 24;
    const int rem = v % 24;
    const int h = rem % 12, b = rem / 12;
    const int u0 = (15 - qt) * 48 + b * 12 + h;       // part 0
    const int u1 = u0 + 24;                           // part 1

    const int row = threadIdx.x;
    const float m1 = Pm[u0 * 128 + row], l1 = Pl[u0 * 128 + row];
    const float m2 = Pm[u1 * 128 + row], l2 = Pl[u1 * 128 + row];
    const float m  = fmaxf(m1, m2);
    const float w1 = __expf(m1 - m), w2 = __expf(m2 - m);
    const float inv = 1.f / fmaf(l1, w1, l2 * w2);
    const float a1 = w1 * inv, a2 = w2 * inv;

    const float* o1 = Po + ((size_t)u0 * 128 + row) * 64;
    const float* o2 = Po + ((size_t)u1 * 128 + row) * 64;
    const int rowg = b * SS + qt * 128 + row;
#pragma unroll
    for (int j = 0; j < 32; j++) {
        const float2 a = ((const float2*)o1)[j];
        const float2 c = ((const float2*)o2)[j];
        const float r0 = fmaf(a.x, a1, c.x * a2);
        const float r1 = fmaf(a.y, a1, c.y * a2);
        *(uint32_t*)(O + toff(rowg, h * HDD + 2 * j, DD / 32)) = pack_f16(r0, r1);
    }
}

// ---------------------------------------------------------------------------
// LayerNorm; SPLIT emits tiled fp16
// ---------------------------------------------------------------------------
template <bool SPLIT>
__global__ void __launch_bounds__(256) ln_kernel(
    const float* __restrict__ in, const float* __restrict__ gw,
    const float* __restrict__ bw, float* __restrict__ out,
    __half* __restrict__ oh)
{
    const int row = blockIdx.x;
    const int t   = threadIdx.x;
    const float* p = in + (size_t)row * DD;

    const float v0 = p[t], v1 = p[t + 256], v2 = p[t + 512];
    float s  = v0 + v1 + v2;
    float sq = fmaf(v0, v0, fmaf(v1, v1, v2 * v2));

#pragma unroll
    for (int off = 16; off; off >>= 1) {
        s  += __shfl_down_sync(0xffffffffu, s, off);
        sq += __shfl_down_sync(0xffffffffu, sq, off);
    }
    __shared__ float rs[8], rq[8];
    __shared__ float mean_s, inv_s;
    const int w = t >> 5, lane = t & 31;
    if (lane == 0) { rs[w] = s; rq[w] = sq; }
    __syncthreads();
    if (t == 0) {
        float S = 0.f, Q = 0.f;
#pragma unroll
        for (int i = 0; i < 8; i++) { S += rs[i]; Q += rq[i]; }
        const float mean = S * (1.f / 768.f);
        const float var  = Q * (1.f / 768.f) - mean * mean;
        mean_s = mean;
        inv_s  = rsqrtf(var + 1e-5f);
    }
    __syncthreads();
    const float mean = mean_s, inv = inv_s;
    float* po = out + (size_t)row * DD;
#pragma unroll
    for (int j = 0; j < 3; j++) {
        const int  c = t + 256 * j;
        const float vj = (j == 0) ? v0 : (j == 1) ? v1 : v2;
        const float r = fmaf((vj - mean) * inv, gw[c], bw[c]);
        po[c] = r;
        if (SPLIT) oh[toff(row, c, DD / 32)] = __float2half_rn(r);
    }
}

// ---------------------------------------------------------------------------
// Launcher
// ---------------------------------------------------------------------------
extern "C" void kernel_launch(void* const* d_in, const int* in_sizes, int n_in,
                              void* d_out, int out_size)
{
    (void)in_sizes; (void)n_in; (void)out_size;
    const float* x     = (const float*)d_in[0];
    const float* alibi = (const float*)d_in[1];
    const float* Wq = (const float*)d_in[2];  const float* bq = (const float*)d_in[3];
    const float* Wk = (const float*)d_in[4];  const float* bk = (const float*)d_in[5];
    const float* Wv = (const float*)d_in[6];  const float* bv = (const float*)d_in[7];
    const float* Wo = (const float*)d_in[8];  const float* bo = (const float*)d_in[9];
    const float* W1 = (const float*)d_in[10]; const float* b1 = (const float*)d_in[11];
    const float* W2 = (const float*)d_in[12]; const float* b2 = (const float*)d_in[13];
    const float* g1w = (const float*)d_in[14]; const float* be1 = (const float*)d_in[15];
    const float* g2w = (const float*)d_in[16]; const float* be2 = (const float*)d_in[17];
    float* out = (float*)d_out;

    float *r1, *y, *z, *po, *pm, *pl;
    cudaGetSymbolAddress((void**)&r1, g_res1);
    cudaGetSymbolAddress((void**)&y,  g_y);
    cudaGetSymbolAddress((void**)&z,  g_z);
    cudaGetSymbolAddress((void**)&po, g_po);
    cudaGetSymbolAddress((void**)&pm, g_pm);
    cudaGetSymbolAddress((void**)&pl, g_pl);

    __half *xh, *ath, *yh, *h1h, *qh, *kh, *vh, *vt;
    __half *wq, *wk, *wv, *wo, *w1, *w2;
    cudaGetSymbolAddress((void**)&xh,  g_xh);
    cudaGetSymbolAddress((void**)&ath, g_ath);
    cudaGetSymbolAddress((void**)&yh,  g_yh);
    cudaGetSymbolAddress((void**)&h1h, g_h1h);
    cudaGetSymbolAddress((void**)&qh,  g_qh);
    cudaGetSymbolAddress((void**)&kh,  g_kh);
    cudaGetSymbolAddress((void**)&vh,  g_vh);
    cudaGetSymbolAddress((void**)&vt,  g_vt);
    cudaGetSymbolAddress((void**)&wq, g_wqT);
    cudaGetSymbolAddress((void**)&wk, g_wkT);
    cudaGetSymbolAddress((void**)&wv, g_wvT);
    cudaGetSymbolAddress((void**)&wo, g_woT);
    cudaGetSymbolAddress((void**)&w1, g_w1T);
    cudaGetSymbolAddress((void**)&w2, g_w2T);

    cudaFuncSetAttribute(gemm_h<M_QKV>, cudaFuncAttributeMaxDynamicSharedMemorySize, GEMM_SMEM);
    cudaFuncSetAttribute(gemm_h<M_WO>,  cudaFuncAttributeMaxDynamicSharedMemorySize, GEMM_SMEM);
    cudaFuncSetAttribute(gemm_h<M_FF1>, cudaFuncAttributeMaxDynamicSharedMemorySize, GEMM_SMEM);
    cudaFuncSetAttribute(gemm_h<M_FF2>, cudaFuncAttributeMaxDynamicSharedMemorySize, GEMM_SMEM);
    cudaFuncSetAttribute(attn_tc, cudaFuncAttributeMaxDynamicSharedMemorySize, ATTN_SMEM);

    const dim3 tb(32, 8);

    Qkv3 qkv;
    qkv.p[0] = {wq, bq, qh};
    qkv.p[1] = {wk, bk, kh};
    qkv.p[2] = {wv, bv, vh};
    Qkv3 dummy = qkv;

    T4 t4;
    t4.W[0] = Wq; t4.T[0] = wq;
    t4.W[1] = Wk; t4.T[1] = wk;
    t4.W[2] = Wv; t4.T[2] = wv;
    t4.W[3] = Wo; t4.T[3] = wo;

    // prep
    convert_h<<<3072, 256>>>(x, xh);
    transpose4_h<<<dim3(24, 24, 4), tb>>>(t4);
    transpose_h<<<dim3(96, 24), tb>>>(W1, w1, DD, DFF);
    transpose_h<<<dim3(24, 96), tb>>>(W2, w2, DFF, DD);

    // fused QKV projections
    gemm_h<M_QKV><<<dim3(6, 32, 3), 256, GEMM_SMEM>>>(
        xh, nullptr, nullptr, nullptr, nullptr, nullptr,
        qkv, NROW, DD, DD);

    vtrans_h<<<dim3(32, 24), 256>>>(vh, vt);

    // split-KV attention + merge
    attn_tc<<<576, 128, ATTN_SMEM>>>(alibi, qh, kh, vt, ath, po, pm, pl);
    attn_merge<<<192, 128>>>(po, pm, pl, ath);

    gemm_h<M_WO><<<dim3(6, 32), 256, GEMM_SMEM>>>(
        ath, wo, bo, x, r1, nullptr, dummy, NROW, DD, DD);
    ln_kernel<true><<<NROW, 256>>>(r1, g1w, be1, y, yh);

    gemm_h<M_FF1><<<dim3(24, 32), 256, GEMM_SMEM>>>(
        yh, w1, b1, nullptr, nullptr, h1h, dummy, NROW, DFF, DD);
    gemm_h<M_FF2><<<dim3(6, 32), 256, GEMM_SMEM>>>(
        h1h, w2, b2, y, z, nullptr, dummy, NROW, DD, DFF);
    ln_kernel<false><<<NROW, 256>>>(z, g2w, be2, out, nullptr);
}

// round 16
// speedup vs baseline: 1.1103x; 1.0557x over previous
#include <cuda_runtime.h>
#include <cuda_fp16.h>
#include <cstdint>
#include <cstddef>

// Problem constants
#define BB    2
#define SS    2048
#define DD    768
#define HH    12
#define HDD   64
#define DFF   3072
#define NROW  4096            // B*S

// GEMM tiling: 128x128 CTA tile, K chunks of 32, tiled global layout.
#define CH     32
#define PADC   40
#define TILE_HW 5120
#define TILE_B  10240
#define G_STAGE_B (2 * TILE_B)             // A + B (single-pass fp16)
#define GEMM_SMEM (3 * G_STAGE_B + 64)     // 3 stages + mbarriers

// attention smem: sk/sv 2x(64x72 half) + alibi 2x(128x68 float)
#define ATTN_SMEM (36864 + 69632)          // 106496 bytes

// split-KV: qt >= 8 handled by 2 CTAs each
#define NSPLIT_U 384                       // 8 qt x 2 parts x 24 (b,h)

#define TSZ(R, K) ((size_t)(R) * (K) / 32 * 40)

// ---------------------------------------------------------------------------
// Scratch (device globals)
// ---------------------------------------------------------------------------
__device__ float g_res1[NROW * DD];
__device__ float g_y[NROW * DD];
__device__ float g_z[NROW * DD];          // FF2 split-K partial 0
__device__ float g_p1[NROW * DD];         // FF2 split-K partial 1

// split-KV partials: per split item u: o[128][64], m[128], l[128]
__device__ float g_po[NSPLIT_U * 128 * 64];
__device__ float g_pm[NSPLIT_U * 128];
__device__ float g_pl[NSPLIT_U * 128];

// tiled fp16 activations
__device__ __half g_xh[TSZ(NROW, DD)];
__device__ __half g_ath[TSZ(NROW, DD)];
__device__ __half g_yh[TSZ(NROW, DD)];
__device__ __half g_h1h[TSZ(NROW, DFF)];

// head-major fp16 q/k/v (linear) + per-head transposed V
__device__ __half g_qh[BB*HH*SS*HDD];
__device__ __half g_kh[BB*HH*SS*HDD];
__device__ __half g_vh[BB*HH*SS*HDD];
__device__ __half g_vt[BB*HH*SS*HDD];     // [bh][hd][s]

// tiled fp16 transposed weights [N, K]
__device__ __half g_wqT[TSZ(DD, DD)];
__device__ __half g_wkT[TSZ(DD, DD)];
__device__ __half g_wvT[TSZ(DD, DD)];
__device__ __half g_woT[TSZ(DD, DD)];
__device__ __half g_w1T[TSZ(DFF, DD)];
__device__ __half g_w2T[TSZ(DD, DFF)];

// ---------------------------------------------------------------------------
// helpers
// ---------------------------------------------------------------------------
__device__ __forceinline__ uint32_t smem_u32(const void* p) {
    uint32_t a;
    asm("{ .reg .u64 t; cvta.to.shared.u64 t, %1; cvt.u32.u64 %0, t; }"
        : "=r"(a) : "l"(p));
    return a;
}
__device__ __forceinline__ void mma16816h(float* d, const uint32_t* a,
                                          uint32_t b0, uint32_t b1) {
    asm volatile(
        "mma.sync.aligned.m16n8k16.row.col.f32.f16.f16.f32 "
        "{%0,%1,%2,%3}, {%4,%5,%6,%7}, {%8,%9}, {%0,%1,%2,%3};"
        : "+f"(d[0]), "+f"(d[1]), "+f"(d[2]), "+f"(d[3])
        : "r"(a[0]), "r"(a[1]), "r"(a[2]), "r"(a[3]), "r"(b0), "r"(b1));
}
__device__ __forceinline__ uint32_t pack_f16(float lo, float hi) {
    uint32_t r;
    asm("cvt.rn.f16x2.f32 %0, %1, %2;" : "=r"(r) : "f"(hi), "f"(lo));
    return r;
}
__device__ __forceinline__ void ldmx4(uint32_t* r, uint32_t addr) {
    asm volatile("ldmatrix.sync.aligned.m8n8.x4.shared.b16 {%0,%1,%2,%3}, [%4];"
                 : "=r"(r[0]), "=r"(r[1]), "=r"(r[2]), "=r"(r[3]) : "r"(addr));
}
__device__ __forceinline__ void mbar_init(uint32_t mbar, uint32_t cnt) {
    asm volatile("mbarrier.init.shared.b64 [%0], %1;" :: "r"(mbar), "r"(cnt) : "memory");
}
__device__ __forceinline__ void mbar_wait(uint32_t mbar, uint32_t parity) {
    asm volatile(
        "{\n\t.reg .pred P;\n\t"
        "WL_%=:\n\t"
        "mbarrier.try_wait.parity.acquire.cta.shared::cta.b64 P, [%0], %1, 0x989680;\n\t"
        "@P bra.uni WD_%=;\n\t"
        "bra.uni WL_%=;\n\t"
        "WD_%=:\n\t}"
        :: "r"(mbar), "r"(parity) : "memory");
}
__device__ __forceinline__ void mbar_expect_tx(uint32_t mbar, uint32_t bytes) {
    asm volatile("mbarrier.arrive.expect_tx.shared.b64 _, [%0], %1;"
                 :: "r"(mbar), "r"(bytes) : "memory");
}
__device__ __forceinline__ void bulkcp(uint32_t dst, const void* src,
                                       uint32_t bytes, uint32_t mbar) {
    asm volatile(
        "cp.async.bulk.shared::cta.global.mbarrier::complete_tx::bytes "
        "[%0], [%1], %2, [%3];"
        :: "r"(dst), "l"(src), "r"(bytes), "r"(mbar) : "memory");
}
__device__ __forceinline__ void cp16(uint32_t dst, const void* src) {
    asm volatile("cp.async.cg.shared.global [%0], [%1], 16;"
                 :: "r"(dst), "l"(src));
}
__device__ __forceinline__ void cp_commit() { asm volatile("cp.async.commit_group;"); }
__device__ __forceinline__ void cp_wait0()  { asm volatile("cp.async.wait_group 0;"); }
__device__ __forceinline__ void cp_wait1()  { asm volatile("cp.async.wait_group 1;"); }

__device__ __forceinline__ size_t toff(int row, int col, int kcn) {
    return (size_t)((row >> 7) * kcn + (col >> 5)) * TILE_HW +
           (row & 127) * PADC + (col & 31);
}

// ---------------------------------------------------------------------------
// fp32 [4096,768] -> tiled fp16
// ---------------------------------------------------------------------------
__global__ void __launch_bounds__(256) convert_h(
    const float* __restrict__ in, __half* __restrict__ oh)
{
    const int i = blockIdx.x * 256 + threadIdx.x;
    const int e = 4 * i;
    const int row = e / DD, col = e - row * DD;
    float4 v = ((const float4*)in)[i];
    const size_t o = toff(row, col, DD / 32);
    *(uint2*)(oh + o) = make_uint2(pack_f16(v.x, v.y), pack_f16(v.z, v.w));
}

// ---------------------------------------------------------------------------
// Fused 4x: W[768,768] fp32 -> tiled Wt[768,768] fp16 (blockIdx.z selects)
// ---------------------------------------------------------------------------
struct T4 { const float* W[4]; __half* T[4]; };

__global__ void __launch_bounds__(256) transpose4_h(T4 p)
{
    __shared__ float tile[32][33];
    const float* W = p.W[blockIdx.z];
    __half* T = p.T[blockIdx.z];
    const int k0 = blockIdx.y * 32, n0 = blockIdx.x * 32;
    const int tx = threadIdx.x, ty = threadIdx.y;   // (32, 8)
#pragma unroll
    for (int i = 0; i < 4; i++)
        tile[ty + 8 * i][tx] = W[(size_t)(k0 + ty + 8 * i) * DD + n0 + tx];
    __syncthreads();
#pragma unroll
    for (int i = 0; i < 4; i++)
        T[toff(n0 + ty + 8 * i, k0 + tx, DD >> 5)] =
            __float2half_rn(tile[tx][ty + 8 * i]);
}

// generic single transpose (W1 / W2)
__global__ void __launch_bounds__(256) transpose_h(
    const float* __restrict__ W, __half* __restrict__ T, int K, int N)
{
    __shared__ float tile[32][33];
    const int k0 = blockIdx.y * 32, n0 = blockIdx.x * 32;
    const int tx = threadIdx.x, ty = threadIdx.y;
#pragma unroll
    for (int i = 0; i < 4; i++)
        tile[ty + 8 * i][tx] = W[(size_t)(k0 + ty + 8 * i) * N + n0 + tx];
    __syncthreads();
    const int kcn = K >> 5;
#pragma unroll
    for (int i = 0; i < 4; i++)
        T[toff(n0 + ty + 8 * i, k0 + tx, kcn)] =
            __float2half_rn(tile[tx][ty + 8 * i]);
}

// ---------------------------------------------------------------------------
// per-head V transpose: [s, hd] -> [hd, s] (fp16, linear)
// ---------------------------------------------------------------------------
__global__ void __launch_bounds__(256) vtrans_h(
    const __half* __restrict__ in, __half* __restrict__ out)
{
    __shared__ uint16_t sm[64][72];
    const int s0 = blockIdx.x * 64;
    const size_t bh = blockIdx.y;
    const uint16_t* src = (const uint16_t*)(in + bh * SS * HDD);
    uint16_t* dst = (uint16_t*)(out + bh * (size_t)HDD * SS);
    const int t = threadIdx.x;
    const int r = t >> 2, cq = (t & 3) * 16;
    *(uint4*)(&sm[r][cq])     = *(const uint4*)(src + (size_t)(s0 + r) * HDD + cq);
    *(uint4*)(&sm[r][cq + 8]) = *(const uint4*)(src + (size_t)(s0 + r) * HDD + cq + 8);
    __syncthreads();
    uint32_t w[8];
#pragma unroll
    for (int j = 0; j < 8; j++)
        w[j] = ((uint32_t)sm[cq + 2 * j + 1][r] << 16) | sm[cq + 2 * j][r];
#pragma unroll
    for (int j = 0; j < 4; j++)
        *(uint2*)(dst + (size_t)r * SS + s0 + cq + 4 * j) =
            make_uint2(w[2 * j], w[2 * j + 1]);
}

// ---------------------------------------------------------------------------
// fp16 1-pass GEMM (proven): 128x128 tile, 8 warps 4(M)x2(N),
// 3-stage bulk-DMA pipeline. M_FF2S = 2-way split-K (blockIdx.z selects half,
// writes raw fp32 partial; bias/residual applied in reduce_ln2).
// ---------------------------------------------------------------------------
#define M_QKV  0
#define M_WO   1
#define M_FF1  2
#define M_FF2S 3

struct PtrQ {
    const __half* b;
    const float* bias;
    __half* c;            // fp16 linear head-major
};
struct Qkv3 { PtrQ p[3]; };

template <int MODE>
__global__ void __launch_bounds__(256) gemm_h(
    const __half* __restrict__ A, const __half* __restrict__ B_,
    const float* __restrict__ bias_, const float* __restrict__ res,
    float* __restrict__ Cf, __half* __restrict__ Ch_,
    Qkv3 qkv, int M, int N, int K)
{
    extern __shared__ char smem[];
    const uint32_t sb = smem_u32(smem);
    const uint32_t mbb = sb + 3 * G_STAGE_B;

    const int t    = threadIdx.x;
    const int lane = t & 31, wid = t >> 5;
    const int wm   = (wid & 3) * 32;
    const int wn   = (wid >> 2) * 64;
    const int bm   = blockIdx.y * 128, bn = blockIdx.x * 128;
    const int g    = lane >> 2, tig = lane & 3;

    const __half* B;
    const float* bias;
    __half* Ch = Ch_;
    if (MODE == M_QKV) {
        const PtrQ& p = qkv.p[blockIdx.z];
        B = p.b; bias = p.bias; Ch = p.c;
    } else {
        B = B_; bias = bias_;
    }

    if (t == 0) { mbar_init(mbb, 1); mbar_init(mbb + 8, 1); mbar_init(mbb + 16, 1); }
    __syncthreads();

    float acc[2][8][4];
#pragma unroll
    for (int i = 0; i < 2; i++)
#pragma unroll
        for (int j = 0; j < 8; j++)
#pragma unroll
            for (int c = 0; c < 4; c++) acc[i][j][c] = 0.f;

    const int KCN = K >> 5;
    const int CN  = (MODE == M_FF2S) ? (KCN >> 1) : KCN;     // chunks this CTA
    const int kc0 = (MODE == M_FF2S) ? (int)blockIdx.z * CN : 0;
    const int arb = bm >> 7, brb = bn >> 7;

    auto issue = [&](int lc, int stage) {                    // lc = local chunk
        if (t == 0) {
            const int gc = kc0 + lc;
            const uint32_t mbar = mbb + stage * 8;
            mbar_expect_tx(mbar, G_STAGE_B);
            const uint32_t d = sb + stage * G_STAGE_B;
            bulkcp(d,          A + ((size_t)arb * KCN + gc) * TILE_HW, TILE_B, mbar);
            bulkcp(d + TILE_B, B + ((size_t)brb * KCN + gc) * TILE_HW, TILE_B, mbar);
        }
    };

    uint32_t ph[3] = {0, 0, 0};
    issue(0, 0);
    if (CN > 1) issue(1, 1);

    const uint32_t lrow = (uint32_t)(lane & 15);
    const uint32_t lcol = (uint32_t)((lane >> 4) * 8);

    for (int c = 0; c < CN; c++) {
        if (c + 2 < CN) issue(c + 2, (c + 2) % 3);
        const int st = c % 3;
        mbar_wait(mbb + st * 8, ph[st]);
        ph[st] ^= 1;

        const uint32_t sA = sb + st * G_STAGE_B;
        const uint32_t sB = sA + TILE_B;

#pragma unroll
        for (int kk = 0; kk < CH; kk += 16) {
            uint32_t a[2][4];
            ldmx4(a[0], sA + ((wm + lrow) * PADC + kk + lcol) * 2);
            ldmx4(a[1], sA + ((wm + 16 + lrow) * PADC + kk + lcol) * 2);
#pragma unroll
            for (int p = 0; p < 4; p++) {
                uint32_t bf[4];
                ldmx4(bf, sB + ((wn + 16 * p + lrow) * PADC + kk + lcol) * 2);
#pragma unroll
                for (int q = 0; q < 2; q++) {
                    const int nt = 2 * p + q;
                    mma16816h(acc[0][nt], a[0], bf[q], bf[q + 2]);
                    mma16816h(acc[1][nt], a[1], bf[q], bf[q + 2]);
                }
            }
        }
        __syncthreads();
    }

    const int okcn = N >> 5;
#pragma unroll
    for (int mt = 0; mt < 2; mt++) {
#pragma unroll
        for (int nt = 0; nt < 8; nt++) {
#pragma unroll
            for (int half = 0; half < 2; half++) {
                const int grow = bm + wm + mt * 16 + g + half * 8;
                const int gcol = bn + wn + nt * 8 + 2 * tig;
                float v0 = acc[mt][nt][half * 2 + 0];
                float v1 = acc[mt][nt][half * 2 + 1];
                if (MODE == M_FF2S) {
                    float* dst = blockIdx.z ? (float*)Ch_ : Cf;
                    *(float2*)(dst + (size_t)grow * N + gcol) =
                        make_float2(v0, v1);
                } else if (MODE == M_QKV) {
                    v0 += bias[gcol];
                    v1 += bias[gcol + 1];
                    const int b_ = grow >> 11, s_ = grow & 2047;
                    const int h_ = gcol >> 6,  hd = gcol & 63;
                    *(uint32_t*)(Ch + (((size_t)(b_ * HH + h_) * SS) + s_) * HDD + hd) =
                        pack_f16(v0, v1);
                } else if (MODE == M_FF1) {
                    v0 = fmaxf(v0 + bias[gcol], 0.f);
                    v1 = fmaxf(v1 + bias[gcol + 1], 0.f);
                    *(uint32_t*)(Ch + toff(grow, gcol, okcn)) = pack_f16(v0, v1);
                } else {
                    const size_t o = (size_t)grow * N + gcol;
                    v0 += bias[gcol]     + res[o];
                    v1 += bias[gcol + 1] + res[o + 1];
                    *(float2*)(Cf + o) = make_float2(v0, v1);
                }
            }
        }
    }
}

// ---------------------------------------------------------------------------
// fp16 flash attention with split-KV for qt >= 8 (R15 proven, unchanged)
// ---------------------------------------------------------------------------
__global__ void __launch_bounds__(128) attn_tc(
    const float* __restrict__ alibi,
    const __half* __restrict__ Q, const __half* __restrict__ K,
    const __half* __restrict__ Vt, __half* __restrict__ O,
    float* __restrict__ Po, float* __restrict__ Pm, float* __restrict__ Pl)
{
    extern __shared__ char smem[];
    __half* skb = (__half*)smem;                   // [2][64*72]
    __half* svb = (__half*)(smem + 18432);         // [2][64*72]
    float*  alb = (float*)(smem + 36864);          // [2][128*68]

    const int t = threadIdx.x, lane = t & 31, wid = t >> 5;
    const int g = lane >> 2, tig = lane & 3;
    const int bx = blockIdx.x;

    int qt, h, b, kt0, kt1, u = -1;
    if (bx < NSPLIT_U) {
        u = bx;
        qt = 15 - u / 48;
        const int part = (u / 24) & 1;
        const int rem = u % 24;
        h = rem % 12;
        b = rem / 12;
        const int nkt = 2 * qt + 2;
        const int mid = nkt >> 1;
        kt0 = part ? mid : 0;
        kt1 = part ? nkt : mid;
    } else {
        const int v = bx - NSPLIT_U;
        qt = 7 - v / 24;
        const int rem = v % 24;
        h = rem % 12;
        b = rem / 12;
        kt0 = 0;
        kt1 = 2 * qt + 2;
    }

    const int q0 = qt * 128, wm = wid * 32;
    const size_t bh = (size_t)(b * HH + h);

    const __half* qb = Q + (bh * SS + q0) * HDD;
    const __half* kb = K + bh * SS * HDD;
    const __half* vb = Vt + bh * (size_t)HDD * SS;
    const float* ab = alibi + (size_t)h * SS * SS;

    uint32_t qf[4][2][4];
#pragma unroll
    for (int kc = 0; kc < 4; kc++)
#pragma unroll
        for (int mt = 0; mt < 2; mt++) {
            const int row = wm + mt * 16 + g;
            qf[kc][mt][0] = *(const uint32_t*)(qb + (size_t)row * HDD + kc * 16 + 2 * tig);
            qf[kc][mt][1] = *(const uint32_t*)(qb + (size_t)(row + 8) * HDD + kc * 16 + 2 * tig);
            qf[kc][mt][2] = *(const uint32_t*)(qb + (size_t)row * HDD + kc * 16 + 8 + 2 * tig);
            qf[kc][mt][3] = *(const uint32_t*)(qb + (size_t)(row + 8) * HDD + kc * 16 + 8 + 2 * tig);
        }

    float o[2][8][4];
#pragma unroll
    for (int i = 0; i < 2; i++)
#pragma unroll
        for (int j = 0; j < 8; j++)
#pragma unroll
            for (int c = 0; c < 4; c++) o[i][j][c] = 0.f;
    float mrow[2][2] = {{-1e30f, -1e30f}, {-1e30f, -1e30f}};
    float lrow[2][2] = {{0.f, 0.f}, {0.f, 0.f}};

    auto prefetch = [&](int kt, int st) {
        const int k0 = kt * 64;
        __half* sk = skb + st * 4608;
        __half* sv = svb + st * 4608;
        float*  sa = alb + st * 8704;
#pragma unroll
        for (int i = 0; i < 4; i++) {
            const int idx = t + 128 * i;
            const int r = idx >> 3, c = (idx & 7) * 8;
            cp16(smem_u32(sk + r * 72 + c), kb + (size_t)(k0 + r) * HDD + c);
            cp16(smem_u32(sv + r * 72 + c), vb + (size_t)r * SS + k0 + c);
        }
#pragma unroll
        for (int i = 0; i < 16; i++) {
            const int idx = t + 128 * i;
            const int r = idx >> 4, c4 = (idx & 15) * 4;
            cp16(smem_u32(sa + r * 68 + c4),
                 ab + (size_t)(q0 + r) * SS + k0 + c4);
        }
        cp_commit();
    };

    prefetch(kt0, 0);

    for (int kt = kt0; kt < kt1; kt++) {
        const int k0 = kt * 64;
        const int st = (kt - kt0) & 1;
        if (kt + 1 < kt1) { prefetch(kt + 1, st ^ 1); cp_wait1(); }
        else              { cp_wait0(); }
        __syncthreads();

        const __half* sk = skb + st * 4608;
        const __half* sv = svb + st * 4608;
        const float*  sa = alb + st * 8704;

        float sacc[2][8][4];
#pragma unroll
        for (int i = 0; i < 2; i++)
#pragma unroll
            for (int j = 0; j < 8; j++)
#pragma unroll
                for (int c = 0; c < 4; c++) sacc[i][j][c] = 0.f;

#pragma unroll
        for (int kc = 0; kc < 4; kc++)
#pragma unroll
            for (int nt = 0; nt < 8; nt++) {
                const __half* kr = sk + (8 * nt + g) * 72 + kc * 16;
                const uint32_t b0 = *(const uint32_t*)(kr + 2 * tig);
                const uint32_t b1 = *(const uint32_t*)(kr + 8 + 2 * tig);
                mma16816h(sacc[0][nt], qf[kc][0], b0, b1);
                mma16816h(sacc[1][nt], qf[kc][1], b0, b1);
            }

#pragma unroll
        for (int mt = 0; mt < 2; mt++)
#pragma unroll
            for (int hf = 0; hf < 2; hf++) {
                const int lrowi = wm + 16 * mt + g + 8 * hf;
                const int rowg  = q0 + lrowi;
                const float* arow = sa + lrowi * 68;
                float mx = -1e30f;
#pragma unroll
                for (int nt = 0; nt < 8; nt++) {
                    const int col = k0 + 8 * nt + 2 * tig;
                    const float2 al2 = *(const float2*)(arow + 8 * nt + 2 * tig);
                    float s0 = fmaf(sacc[mt][nt][2 * hf + 0], 0.125f, al2.x);
                    float s1 = fmaf(sacc[mt][nt][2 * hf + 1], 0.125f, al2.y);
                    if (col > rowg)     s0 = -1e30f;
                    if (col + 1 > rowg) s1 = -1e30f;
                    sacc[mt][nt][2 * hf + 0] = s0;
                    sacc[mt][nt][2 * hf + 1] = s1;
                    mx = fmaxf(mx, fmaxf(s0, s1));
                }
                mx = fmaxf(mx, __shfl_xor_sync(0xffffffffu, mx, 1));
                mx = fmaxf(mx, __shfl_xor_sync(0xffffffffu, mx, 2));
                const float mn = fmaxf(mrow[mt][hf], mx);
                const float corr = __expf(mrow[mt][hf] - mn);
                mrow[mt][hf] = mn;
                lrow[mt][hf] *= corr;
#pragma unroll
                for (int nt = 0; nt < 8; nt++) {
                    o[mt][nt][2 * hf + 0] *= corr;
                    o[mt][nt][2 * hf + 1] *= corr;
                }
                float ls = 0.f;
#pragma unroll
                for (int nt = 0; nt < 8; nt++) {
                    const float p0 = __expf(sacc[mt][nt][2 * hf + 0] - mn);
                    const float p1 = __expf(sacc[mt][nt][2 * hf + 1] - mn);
                    sacc[mt][nt][2 * hf + 0] = p0;
                    sacc[mt][nt][2 * hf + 1] = p1;
                    ls += p0 + p1;
                }
                ls += __shfl_xor_sync(0xffffffffu, ls, 1);
                ls += __shfl_xor_sync(0xffffffffu, ls, 2);
                lrow[mt][hf] += ls;
            }

#pragma unroll
        for (int kc = 0; kc < 4; kc++) {
            uint32_t ap[2][4];
#pragma unroll
            for (int mt = 0; mt < 2; mt++)
#pragma unroll
                for (int q2 = 0; q2 < 2; q2++) {
                    const float* pp = sacc[mt][2 * kc + q2];
                    ap[mt][2 * q2 + 0] = pack_f16(pp[0], pp[1]);
                    ap[mt][2 * q2 + 1] = pack_f16(pp[2], pp[3]);
                }
#pragma unroll
            for (int nt = 0; nt < 8; nt++) {
                const __half* vr = sv + (8 * nt + g) * 72 + kc * 16;
                const uint32_t b0 = *(const uint32_t*)(vr + 2 * tig);
                const uint32_t b1 = *(const uint32_t*)(vr + 8 + 2 * tig);
                mma16816h(o[0][nt], ap[0], b0, b1);
                mma16816h(o[1][nt], ap[1], b0, b1);
            }
        }
        __syncthreads();
    }

    if (u >= 0) {
        float* pob = Po + (size_t)u * 128 * 64;
#pragma unroll
        for (int mt = 0; mt < 2; mt++)
#pragma unroll
            for (int hf = 0; hf < 2; hf++) {
                const int lrowi = wm + 16 * mt + g + 8 * hf;
                if (tig == 0) {
                    Pm[u * 128 + lrowi] = mrow[mt][hf];
                    Pl[u * 128 + lrowi] = lrow[mt][hf];
                }
#pragma unroll
                for (int nt = 0; nt < 8; nt++)
                    *(float2*)(pob + lrowi * 64 + 8 * nt + 2 * tig) =
                        make_float2(o[mt][nt][2 * hf + 0],
                                    o[mt][nt][2 * hf + 1]);
            }
    } else {
#pragma unroll
        for (int mt = 0; mt < 2; mt++)
#pragma unroll
            for (int hf = 0; hf < 2; hf++) {
                const float inv = 1.f / lrow[mt][hf];
                const int rowg = b * SS + q0 + wm + 16 * mt + g + 8 * hf;
#pragma unroll
                for (int nt = 0; nt < 8; nt++) {
                    const int col = h * HDD + 8 * nt + 2 * tig;
                    *(uint32_t*)(O + toff(rowg, col, DD / 32)) =
                        pack_f16(o[mt][nt][2 * hf + 0] * inv,
                                 o[mt][nt][2 * hf + 1] * inv);
                }
            }
    }
}

// ---------------------------------------------------------------------------
// split-KV merge (R15 proven)
// ---------------------------------------------------------------------------
__global__ void __launch_bounds__(128) attn_merge(
    const float* __restrict__ Po, const float* __restrict__ Pm,
    const float* __restrict__ Pl, __half* __restrict__ O)
{
    const int v = blockIdx.x;
    const int qt = 15 - v / 24;
    const int rem = v % 24;
    const int h = rem % 12, b = rem / 12;
    const int u0 = (15 - qt) * 48 + b * 12 + h;
    const int u1 = u0 + 24;

    const int row = threadIdx.x;
    const float m1 = Pm[u0 * 128 + row], l1 = Pl[u0 * 128 + row];
    const float m2 = Pm[u1 * 128 + row], l2 = Pl[u1 * 128 + row];
    const float m  = fmaxf(m1, m2);
    const float w1 = __expf(m1 - m), w2 = __expf(m2 - m);
    const float inv = 1.f / fmaf(l1, w1, l2 * w2);
    const float a1 = w1 * inv, a2 = w2 * inv;

    const float* o1 = Po + ((size_t)u0 * 128 + row) * 64;
    const float* o2 = Po + ((size_t)u1 * 128 + row) * 64;
    const int rowg = b * SS + qt * 128 + row;
#pragma unroll
    for (int j = 0; j < 32; j++) {
        const float2 a = ((const float2*)o1)[j];
        const float2 c = ((const float2*)o2)[j];
        const float r0 = fmaf(a.x, a1, c.x * a2);
        const float r1 = fmaf(a.y, a1, c.y * a2);
        *(uint32_t*)(O + toff(rowg, h * HDD + 2 * j, DD / 32)) = pack_f16(r0, r1);
    }
}

// ---------------------------------------------------------------------------
// LayerNorm (LN1 path); SPLIT emits tiled fp16
// ---------------------------------------------------------------------------
template <bool SPLIT>
__global__ void __launch_bounds__(256) ln_kernel(
    const float* __restrict__ in, const float* __restrict__ gw,
    const float* __restrict__ bw, float* __restrict__ out,
    __half* __restrict__ oh)
{
    const int row = blockIdx.x;
    const int t   = threadIdx.x;
    const float* p = in + (size_t)row * DD;

    const float v0 = p[t], v1 = p[t + 256], v2 = p[t + 512];
    float s  = v0 + v1 + v2;
    float sq = fmaf(v0, v0, fmaf(v1, v1, v2 * v2));

#pragma unroll
    for (int off = 16; off; off >>= 1) {
        s  += __shfl_down_sync(0xffffffffu, s, off);
        sq += __shfl_down_sync(0xffffffffu, sq, off);
    }
    __shared__ float rs[8], rq[8];
    __shared__ float mean_s, inv_s;
    const int w = t >> 5, lane = t & 31;
    if (lane == 0) { rs[w] = s; rq[w] = sq; }
    __syncthreads();
    if (t == 0) {
        float S = 0.f, Q = 0.f;
#pragma unroll
        for (int i = 0; i < 8; i++) { S += rs[i]; Q += rq[i]; }
        const float mean = S * (1.f / 768.f);
        const float var  = Q * (1.f / 768.f) - mean * mean;
        mean_s = mean;
        inv_s  = rsqrtf(var + 1e-5f);
    }
    __syncthreads();
    const float mean = mean_s, inv = inv_s;
    float* po = out + (size_t)row * DD;
#pragma unroll
    for (int j = 0; j < 3; j++) {
        const int  c = t + 256 * j;
        const float vj = (j == 0) ? v0 : (j == 1) ? v1 : v2;
        const float r = fmaf((vj - mean) * inv, gw[c], bw[c]);
        po[c] = r;
        if (SPLIT) oh[toff(row, c, DD / 32)] = __float2half_rn(r);
    }
}

// ---------------------------------------------------------------------------
// Fused FF2 split-K reduce + bias + residual + LayerNorm2 -> out
// ---------------------------------------------------------------------------
__global__ void __launch_bounds__(256) reduce_ln2(
    const float* __restrict__ p0, const float* __restrict__ p1,
    const float* __restrict__ bias, const float* __restrict__ resid,
    const float* __restrict__ gw, const float* __restrict__ bw,
    float* __restrict__ out)
{
    const int row = blockIdx.x;
    const int t   = threadIdx.x;
    const size_t base = (size_t)row * DD;

    float v[3];
#pragma unroll
    for (int j = 0; j < 3; j++) {
        const int c = t + 256 * j;
        v[j] = p0[base + c] + p1[base + c] + bias[c] + resid[base + c];
    }
    float s  = v[0] + v[1] + v[2];
    float sq = fmaf(v[0], v[0], fmaf(v[1], v[1], v[2] * v[2]));

#pragma unroll
    for (int off = 16; off; off >>= 1) {
        s  += __shfl_down_sync(0xffffffffu, s, off);
        sq += __shfl_down_sync(0xffffffffu, sq, off);
    }
    __shared__ float rs[8], rq[8];
    __shared__ float mean_s, inv_s;
    const int w = t >> 5, lane = t & 31;
    if (lane == 0) { rs[w] = s; rq[w] = sq; }
    __syncthreads();
    if (t == 0) {
        float S = 0.f, Q = 0.f;
#pragma unroll
        for (int i = 0; i < 8; i++) { S += rs[i]; Q += rq[i]; }
        const float mean = S * (1.f / 768.f);
        const float var  = Q * (1.f / 768.f) - mean * mean;
        mean_s = mean;
        inv_s  = rsqrtf(var + 1e-5f);
    }
    __syncthreads();
    const float mean = mean_s, inv = inv_s;
#pragma unroll
    for (int j = 0; j < 3; j++) {
        const int c = t + 256 * j;
        out[base + c] = fmaf((v[j] - mean) * inv, gw[c], bw[c]);
    }
}

// ---------------------------------------------------------------------------
// Launcher
// ---------------------------------------------------------------------------
extern "C" void kernel_launch(void* const* d_in, const int* in_sizes, int n_in,
                              void* d_out, int out_size)
{
    (void)in_sizes; (void)n_in; (void)out_size;
    const float* x     = (const float*)d_in[0];
    const float* alibi = (const float*)d_in[1];
    const float* Wq = (const float*)d_in[2];  const float* bq = (const float*)d_in[3];
    const float* Wk = (const float*)d_in[4];  const float* bk = (const float*)d_in[5];
    const float* Wv = (const float*)d_in[6];  const float* bv = (const float*)d_in[7];
    const float* Wo = (const float*)d_in[8];  const float* bo = (const float*)d_in[9];
    const float* W1 = (const float*)d_in[10]; const float* b1 = (const float*)d_in[11];
    const float* W2 = (const float*)d_in[12]; const float* b2 = (const float*)d_in[13];
    const float* g1w = (const float*)d_in[14]; const float* be1 = (const float*)d_in[15];
    const float* g2w = (const float*)d_in[16]; const float* be2 = (const float*)d_in[17];
    float* out = (float*)d_out;

    float *r1, *y, *z, *p1f, *po, *pm, *pl;
    cudaGetSymbolAddress((void**)&r1, g_res1);
    cudaGetSymbolAddress((void**)&y,  g_y);
    cudaGetSymbolAddress((void**)&z,  g_z);
    cudaGetSymbolAddress((void**)&p1f, g_p1);
    cudaGetSymbolAddress((void**)&po, g_po);
    cudaGetSymbolAddress((void**)&pm, g_pm);
    cudaGetSymbolAddress((void**)&pl, g_pl);

    __half *xh, *ath, *yh, *h1h, *qh, *kh, *vh, *vt;
    __half *wq, *wk, *wv, *wo, *w1, *w2;
    cudaGetSymbolAddress((void**)&xh,  g_xh);
    cudaGetSymbolAddress((void**)&ath, g_ath);
    cudaGetSymbolAddress((void**)&yh,  g_yh);
    cudaGetSymbolAddress((void**)&h1h, g_h1h);
    cudaGetSymbolAddress((void**)&qh,  g_qh);
    cudaGetSymbolAddress((void**)&kh,  g_kh);
    cudaGetSymbolAddress((void**)&vh,  g_vh);
    cudaGetSymbolAddress((void**)&vt,  g_vt);
    cudaGetSymbolAddress((void**)&wq, g_wqT);
    cudaGetSymbolAddress((void**)&wk, g_wkT);
    cudaGetSymbolAddress((void**)&wv, g_wvT);
    cudaGetSymbolAddress((void**)&wo, g_woT);
    cudaGetSymbolAddress((void**)&w1, g_w1T);
    cudaGetSymbolAddress((void**)&w2, g_w2T);

    cudaFuncSetAttribute(gemm_h<M_QKV>,  cudaFuncAttributeMaxDynamicSharedMemorySize, GEMM_SMEM);
    cudaFuncSetAttribute(gemm_h<M_WO>,   cudaFuncAttributeMaxDynamicSharedMemorySize, GEMM_SMEM);
    cudaFuncSetAttribute(gemm_h<M_FF1>,  cudaFuncAttributeMaxDynamicSharedMemorySize, GEMM_SMEM);
    cudaFuncSetAttribute(gemm_h<M_FF2S>, cudaFuncAttributeMaxDynamicSharedMemorySize, GEMM_SMEM);
    cudaFuncSetAttribute(attn_tc, cudaFuncAttributeMaxDynamicSharedMemorySize, ATTN_SMEM);

    const dim3 tb(32, 8);

    Qkv3 qkv;
    qkv.p[0] = {wq, bq, qh};
    qkv.p[1] = {wk, bk, kh};
    qkv.p[2] = {wv, bv, vh};
    Qkv3 dummy = qkv;

    T4 t4;
    t4.W[0] = Wq; t4.T[0] = wq;
    t4.W[1] = Wk; t4.T[1] = wk;
    t4.W[2] = Wv; t4.T[2] = wv;
    t4.W[3] = Wo; t4.T[3] = wo;

    // prep
    convert_h<<<3072, 256>>>(x, xh);
    transpose4_h<<<dim3(24, 24, 4), tb>>>(t4);
    transpose_h<<<dim3(96, 24), tb>>>(W1, w1, DD, DFF);
    transpose_h<<<dim3(24, 96), tb>>>(W2, w2, DFF, DD);

    // fused QKV projections
    gemm_h<M_QKV><<<dim3(6, 32, 3), 256, GEMM_SMEM>>>(
        xh, nullptr, nullptr, nullptr, nullptr, nullptr,
        qkv, NROW, DD, DD);

    vtrans_h<<<dim3(32, 24), 256>>>(vh, vt);

    // split-KV attention + merge
    attn_tc<<<576, 128, ATTN_SMEM>>>(alibi, qh, kh, vt, ath, po, pm, pl);
    attn_merge<<<192, 128>>>(po, pm, pl, ath);

    gemm_h<M_WO><<<dim3(6, 32), 256, GEMM_SMEM>>>(
        ath, wo, bo, x, r1, nullptr, dummy, NROW, DD, DD);
    ln_kernel<true><<<NROW, 256>>>(r1, g1w, be1, y, yh);

    gemm_h<M_FF1><<<dim3(24, 32), 256, GEMM_SMEM>>>(
        yh, w1, b1, nullptr, nullptr, h1h, dummy, NROW, DFF, DD);

    // FF2: 2-way split-K -> fp32 partials z / p1f, then fused reduce+LN2
    gemm_h<M_FF2S><<<dim3(6, 32, 2), 256, GEMM_SMEM>>>(
        h1h, w2, nullptr, nullptr, z, (__half*)p1f, dummy, NROW, DD, DFF);
    reduce_ln2<<<NROW, 256>>>(z, p1f, b2, y, g2w, be2, out);
}

// round 17
// speedup vs baseline: 1.1280x; 1.0160x over previous
#include <cuda_runtime.h>
#include <cuda_fp16.h>
#include <cstdint>
#include <cstddef>

// Problem constants
#define BB    2
#define SS    2048
#define DD    768
#define HH    12
#define HDD   64
#define DFF   3072
#define NROW  4096            // B*S

// GEMM tiling: 128x128 CTA tile, K chunks of 32, tiled global layout.
#define CH     32
#define PADC   40
#define TILE_HW 5120
#define TILE_B  10240
#define G_STAGE_B (2 * TILE_B)             // A + B (single-pass fp16)
#define GEMM_SMEM (3 * G_STAGE_B + 64)     // 3 stages + mbarriers

// attention smem: sk/sv 2x(64x72 half) + alibi 2x(128x68 float)
#define ATTN_SMEM (36864 + 69632)          // 106496 bytes

// split-KV: qt >= 8 handled by 2 CTAs each
#define NSPLIT_U 384                       // 8 qt x 2 parts x 24 (b,h)

#define TSZ(R, K) ((size_t)(R) * (K) / 32 * 40)

// ---------------------------------------------------------------------------
// Scratch (device globals)
// ---------------------------------------------------------------------------
__device__ float g_y[NROW * DD];
__device__ float g_z[NROW * DD];          // split-K partial 0 (WO, then FF2)
__device__ float g_p1[NROW * DD];         // split-K partial 1

// split-KV partials: per split item u: o[128][64], m[128], l[128]
__device__ float g_po[NSPLIT_U * 128 * 64];
__device__ float g_pm[NSPLIT_U * 128];
__device__ float g_pl[NSPLIT_U * 128];

// tiled fp16 activations
__device__ __half g_xh[TSZ(NROW, DD)];
__device__ __half g_ath[TSZ(NROW, DD)];
__device__ __half g_yh[TSZ(NROW, DD)];
__device__ __half g_h1h[TSZ(NROW, DFF)];

// head-major fp16 q/k/v (linear) + per-head transposed V
__device__ __half g_qh[BB*HH*SS*HDD];
__device__ __half g_kh[BB*HH*SS*HDD];
__device__ __half g_vh[BB*HH*SS*HDD];
__device__ __half g_vt[BB*HH*SS*HDD];     // [bh][hd][s]

// tiled fp16 transposed weights [N, K]
__device__ __half g_wqT[TSZ(DD, DD)];
__device__ __half g_wkT[TSZ(DD, DD)];
__device__ __half g_wvT[TSZ(DD, DD)];
__device__ __half g_woT[TSZ(DD, DD)];
__device__ __half g_w1T[TSZ(DFF, DD)];
__device__ __half g_w2T[TSZ(DD, DFF)];

// ---------------------------------------------------------------------------
// helpers
// ---------------------------------------------------------------------------
__device__ __forceinline__ uint32_t smem_u32(const void* p) {
    uint32_t a;
    asm("{ .reg .u64 t; cvta.to.shared.u64 t, %1; cvt.u32.u64 %0, t; }"
        : "=r"(a) : "l"(p));
    return a;
}
__device__ __forceinline__ void mma16816h(float* d, const uint32_t* a,
                                          uint32_t b0, uint32_t b1) {
    asm volatile(
        "mma.sync.aligned.m16n8k16.row.col.f32.f16.f16.f32 "
        "{%0,%1,%2,%3}, {%4,%5,%6,%7}, {%8,%9}, {%0,%1,%2,%3};"
        : "+f"(d[0]), "+f"(d[1]), "+f"(d[2]), "+f"(d[3])
        : "r"(a[0]), "r"(a[1]), "r"(a[2]), "r"(a[3]), "r"(b0), "r"(b1));
}
__device__ __forceinline__ uint32_t pack_f16(float lo, float hi) {
    uint32_t r;
    asm("cvt.rn.f16x2.f32 %0, %1, %2;" : "=r"(r) : "f"(hi), "f"(lo));
    return r;
}
__device__ __forceinline__ void ldmx4(uint32_t* r, uint32_t addr) {
    asm volatile("ldmatrix.sync.aligned.m8n8.x4.shared.b16 {%0,%1,%2,%3}, [%4];"
                 : "=r"(r[0]), "=r"(r[1]), "=r"(r[2]), "=r"(r[3]) : "r"(addr));
}
__device__ __forceinline__ void mbar_init(uint32_t mbar, uint32_t cnt) {
    asm volatile("mbarrier.init.shared.b64 [%0], %1;" :: "r"(mbar), "r"(cnt) : "memory");
}
__device__ __forceinline__ void mbar_wait(uint32_t mbar, uint32_t parity) {
    asm volatile(
        "{\n\t.reg .pred P;\n\t"
        "WL_%=:\n\t"
        "mbarrier.try_wait.parity.acquire.cta.shared::cta.b64 P, [%0], %1, 0x989680;\n\t"
        "@P bra.uni WD_%=;\n\t"
        "bra.uni WL_%=;\n\t"
        "WD_%=:\n\t}"
        :: "r"(mbar), "r"(parity) : "memory");
}
__device__ __forceinline__ void mbar_expect_tx(uint32_t mbar, uint32_t bytes) {
    asm volatile("mbarrier.arrive.expect_tx.shared.b64 _, [%0], %1;"
                 :: "r"(mbar), "r"(bytes) : "memory");
}
__device__ __forceinline__ void bulkcp(uint32_t dst, const void* src,
                                       uint32_t bytes, uint32_t mbar) {
    asm volatile(
        "cp.async.bulk.shared::cta.global.mbarrier::complete_tx::bytes "
        "[%0], [%1], %2, [%3];"
        :: "r"(dst), "l"(src), "r"(bytes), "r"(mbar) : "memory");
}
__device__ __forceinline__ void cp16(uint32_t dst, const void* src) {
    asm volatile("cp.async.cg.shared.global [%0], [%1], 16;"
                 :: "r"(dst), "l"(src));
}
__device__ __forceinline__ void cp_commit() { asm volatile("cp.async.commit_group;"); }
__device__ __forceinline__ void cp_wait0()  { asm volatile("cp.async.wait_group 0;"); }
__device__ __forceinline__ void cp_wait1()  { asm volatile("cp.async.wait_group 1;"); }

__device__ __forceinline__ size_t toff(int row, int col, int kcn) {
    return (size_t)((row >> 7) * kcn + (col >> 5)) * TILE_HW +
           (row & 127) * PADC + (col & 31);
}

// ---------------------------------------------------------------------------
// fp32 [4096,768] -> tiled fp16
// ---------------------------------------------------------------------------
__global__ void __launch_bounds__(256) convert_h(
    const float* __restrict__ in, __half* __restrict__ oh)
{
    const int i = blockIdx.x * 256 + threadIdx.x;
    const int e = 4 * i;
    const int row = e / DD, col = e - row * DD;
    float4 v = ((const float4*)in)[i];
    const size_t o = toff(row, col, DD / 32);
    *(uint2*)(oh + o) = make_uint2(pack_f16(v.x, v.y), pack_f16(v.z, v.w));
}

// ---------------------------------------------------------------------------
// Fused 4x: W[768,768] fp32 -> tiled Wt[768,768] fp16 (blockIdx.z selects)
// ---------------------------------------------------------------------------
struct T4 { const float* W[4]; __half* T[4]; };

__global__ void __launch_bounds__(256) transpose4_h(T4 p)
{
    __shared__ float tile[32][33];
    const float* W = p.W[blockIdx.z];
    __half* T = p.T[blockIdx.z];
    const int k0 = blockIdx.y * 32, n0 = blockIdx.x * 32;
    const int tx = threadIdx.x, ty = threadIdx.y;   // (32, 8)
#pragma unroll
    for (int i = 0; i < 4; i++)
        tile[ty + 8 * i][tx] = W[(size_t)(k0 + ty + 8 * i) * DD + n0 + tx];
    __syncthreads();
#pragma unroll
    for (int i = 0; i < 4; i++)
        T[toff(n0 + ty + 8 * i, k0 + tx, DD >> 5)] =
            __float2half_rn(tile[tx][ty + 8 * i]);
}

// generic single transpose (W1 / W2)
__global__ void __launch_bounds__(256) transpose_h(
    const float* __restrict__ W, __half* __restrict__ T, int K, int N)
{
    __shared__ float tile[32][33];
    const int k0 = blockIdx.y * 32, n0 = blockIdx.x * 32;
    const int tx = threadIdx.x, ty = threadIdx.y;
#pragma unroll
    for (int i = 0; i < 4; i++)
        tile[ty + 8 * i][tx] = W[(size_t)(k0 + ty + 8 * i) * N + n0 + tx];
    __syncthreads();
    const int kcn = K >> 5;
#pragma unroll
    for (int i = 0; i < 4; i++)
        T[toff(n0 + ty + 8 * i, k0 + tx, kcn)] =
            __float2half_rn(tile[tx][ty + 8 * i]);
}

// ---------------------------------------------------------------------------
// per-head V transpose: [s, hd] -> [hd, s] (fp16, linear)
// ---------------------------------------------------------------------------
__global__ void __launch_bounds__(256) vtrans_h(
    const __half* __restrict__ in, __half* __restrict__ out)
{
    __shared__ uint16_t sm[64][72];
    const int s0 = blockIdx.x * 64;
    const size_t bh = blockIdx.y;
    const uint16_t* src = (const uint16_t*)(in + bh * SS * HDD);
    uint16_t* dst = (uint16_t*)(out + bh * (size_t)HDD * SS);
    const int t = threadIdx.x;
    const int r = t >> 2, cq = (t & 3) * 16;
    *(uint4*)(&sm[r][cq])     = *(const uint4*)(src + (size_t)(s0 + r) * HDD + cq);
    *(uint4*)(&sm[r][cq + 8]) = *(const uint4*)(src + (size_t)(s0 + r) * HDD + cq + 8);
    __syncthreads();
    uint32_t w[8];
#pragma unroll
    for (int j = 0; j < 8; j++)
        w[j] = ((uint32_t)sm[cq + 2 * j + 1][r] << 16) | sm[cq + 2 * j][r];
#pragma unroll
    for (int j = 0; j < 4; j++)
        *(uint2*)(dst + (size_t)r * SS + s0 + cq + 4 * j) =
            make_uint2(w[2 * j], w[2 * j + 1]);
}

// ---------------------------------------------------------------------------
// fp16 1-pass GEMM: 128x128 tile, 8 warps 4(M)x2(N), 3-stage bulk-DMA pipeline.
// M_SPLITK = 2-way split-K (blockIdx.z selects half, writes raw fp32 partial).
// ---------------------------------------------------------------------------
#define M_QKV    0
#define M_FF1    2
#define M_SPLITK 3

struct PtrQ {
    const __half* b;
    const float* bias;
    __half* c;            // fp16 linear head-major
};
struct Qkv3 { PtrQ p[3]; };

template <int MODE>
__global__ void __launch_bounds__(256) gemm_h(
    const __half* __restrict__ A, const __half* __restrict__ B_,
    const float* __restrict__ bias_, const float* __restrict__ res,
    float* __restrict__ Cf, __half* __restrict__ Ch_,
    Qkv3 qkv, int M, int N, int K)
{
    extern __shared__ char smem[];
    const uint32_t sb = smem_u32(smem);
    const uint32_t mbb = sb + 3 * G_STAGE_B;

    const int t    = threadIdx.x;
    const int lane = t & 31, wid = t >> 5;
    const int wm   = (wid & 3) * 32;
    const int wn   = (wid >> 2) * 64;
    const int bm   = blockIdx.y * 128, bn = blockIdx.x * 128;
    const int g    = lane >> 2, tig = lane & 3;

    const __half* B;
    const float* bias;
    __half* Ch = Ch_;
    if (MODE == M_QKV) {
        const PtrQ& p = qkv.p[blockIdx.z];
        B = p.b; bias = p.bias; Ch = p.c;
    } else {
        B = B_; bias = bias_;
    }

    if (t == 0) { mbar_init(mbb, 1); mbar_init(mbb + 8, 1); mbar_init(mbb + 16, 1); }
    __syncthreads();

    float acc[2][8][4];
#pragma unroll
    for (int i = 0; i < 2; i++)
#pragma unroll
        for (int j = 0; j < 8; j++)
#pragma unroll
            for (int c = 0; c < 4; c++) acc[i][j][c] = 0.f;

    const int KCN = K >> 5;
    const int CN  = (MODE == M_SPLITK) ? (KCN >> 1) : KCN;
    const int kc0 = (MODE == M_SPLITK) ? (int)blockIdx.z * CN : 0;
    const int arb = bm >> 7, brb = bn >> 7;

    auto issue = [&](int lc, int stage) {
        if (t == 0) {
            const int gc = kc0 + lc;
            const uint32_t mbar = mbb + stage * 8;
            mbar_expect_tx(mbar, G_STAGE_B);
            const uint32_t d = sb + stage * G_STAGE_B;
            bulkcp(d,          A + ((size_t)arb * KCN + gc) * TILE_HW, TILE_B, mbar);
            bulkcp(d + TILE_B, B + ((size_t)brb * KCN + gc) * TILE_HW, TILE_B, mbar);
        }
    };

    uint32_t ph[3] = {0, 0, 0};
    issue(0, 0);
    if (CN > 1) issue(1, 1);

    const uint32_t lrow = (uint32_t)(lane & 15);
    const uint32_t lcol = (uint32_t)((lane >> 4) * 8);

    for (int c = 0; c < CN; c++) {
        if (c + 2 < CN) issue(c + 2, (c + 2) % 3);
        const int st = c % 3;
        mbar_wait(mbb + st * 8, ph[st]);
        ph[st] ^= 1;

        const uint32_t sA = sb + st * G_STAGE_B;
        const uint32_t sB = sA + TILE_B;

#pragma unroll
        for (int kk = 0; kk < CH; kk += 16) {
            uint32_t a[2][4];
            ldmx4(a[0], sA + ((wm + lrow) * PADC + kk + lcol) * 2);
            ldmx4(a[1], sA + ((wm + 16 + lrow) * PADC + kk + lcol) * 2);
#pragma unroll
            for (int p = 0; p < 4; p++) {
                uint32_t bf[4];
                ldmx4(bf, sB + ((wn + 16 * p + lrow) * PADC + kk + lcol) * 2);
#pragma unroll
                for (int q = 0; q < 2; q++) {
                    const int nt = 2 * p + q;
                    mma16816h(acc[0][nt], a[0], bf[q], bf[q + 2]);
                    mma16816h(acc[1][nt], a[1], bf[q], bf[q + 2]);
                }
            }
        }
        __syncthreads();
    }

    const int okcn = N >> 5;
#pragma unroll
    for (int mt = 0; mt < 2; mt++) {
#pragma unroll
        for (int nt = 0; nt < 8; nt++) {
#pragma unroll
            for (int half = 0; half < 2; half++) {
                const int grow = bm + wm + mt * 16 + g + half * 8;
                const int gcol = bn + wn + nt * 8 + 2 * tig;
                float v0 = acc[mt][nt][half * 2 + 0];
                float v1 = acc[mt][nt][half * 2 + 1];
                if (MODE == M_SPLITK) {
                    float* dst = blockIdx.z ? (float*)Ch_ : Cf;
                    *(float2*)(dst + (size_t)grow * N + gcol) =
                        make_float2(v0, v1);
                } else if (MODE == M_QKV) {
                    v0 += bias[gcol];
                    v1 += bias[gcol + 1];
                    const int b_ = grow >> 11, s_ = grow & 2047;
                    const int h_ = gcol >> 6,  hd = gcol & 63;
                    *(uint32_t*)(Ch + (((size_t)(b_ * HH + h_) * SS) + s_) * HDD + hd) =
                        pack_f16(v0, v1);
                } else {  // M_FF1
                    v0 = fmaxf(v0 + bias[gcol], 0.f);
                    v1 = fmaxf(v1 + bias[gcol + 1], 0.f);
                    *(uint32_t*)(Ch + toff(grow, gcol, okcn)) = pack_f16(v0, v1);
                }
            }
        }
    }
}

// ---------------------------------------------------------------------------
// fp16 flash attention with split-KV for qt >= 8 (proven, unchanged)
// ---------------------------------------------------------------------------
__global__ void __launch_bounds__(128) attn_tc(
    const float* __restrict__ alibi,
    const __half* __restrict__ Q, const __half* __restrict__ K,
    const __half* __restrict__ Vt, __half* __restrict__ O,
    float* __restrict__ Po, float* __restrict__ Pm, float* __restrict__ Pl)
{
    extern __shared__ char smem[];
    __half* skb = (__half*)smem;                   // [2][64*72]
    __half* svb = (__half*)(smem + 18432);         // [2][64*72]
    float*  alb = (float*)(smem + 36864);          // [2][128*68]

    const int t = threadIdx.x, lane = t & 31, wid = t >> 5;
    const int g = lane >> 2, tig = lane & 3;
    const int bx = blockIdx.x;

    int qt, h, b, kt0, kt1, u = -1;
    if (bx < NSPLIT_U) {
        u = bx;
        qt = 15 - u / 48;
        const int part = (u / 24) & 1;
        const int rem = u % 24;
        h = rem % 12;
        b = rem / 12;
        const int nkt = 2 * qt + 2;
        const int mid = nkt >> 1;
        kt0 = part ? mid : 0;
        kt1 = part ? nkt : mid;
    } else {
        const int v = bx - NSPLIT_U;
        qt = 7 - v / 24;
        const int rem = v % 24;
        h = rem % 12;
        b = rem / 12;
        kt0 = 0;
        kt1 = 2 * qt + 2;
    }

    const int q0 = qt * 128, wm = wid * 32;
    const size_t bh = (size_t)(b * HH + h);

    const __half* qb = Q + (bh * SS + q0) * HDD;
    const __half* kb = K + bh * SS * HDD;
    const __half* vb = Vt + bh * (size_t)HDD * SS;
    const float* ab = alibi + (size_t)h * SS * SS;

    uint32_t qf[4][2][4];
#pragma unroll
    for (int kc = 0; kc < 4; kc++)
#pragma unroll
        for (int mt = 0; mt < 2; mt++) {
            const int row = wm + mt * 16 + g;
            qf[kc][mt][0] = *(const uint32_t*)(qb + (size_t)row * HDD + kc * 16 + 2 * tig);
            qf[kc][mt][1] = *(const uint32_t*)(qb + (size_t)(row + 8) * HDD + kc * 16 + 2 * tig);
            qf[kc][mt][2] = *(const uint32_t*)(qb + (size_t)row * HDD + kc * 16 + 8 + 2 * tig);
            qf[kc][mt][3] = *(const uint32_t*)(qb + (size_t)(row + 8) * HDD + kc * 16 + 8 + 2 * tig);
        }

    float o[2][8][4];
#pragma unroll
    for (int i = 0; i < 2; i++)
#pragma unroll
        for (int j = 0; j < 8; j++)
#pragma unroll
            for (int c = 0; c < 4; c++) o[i][j][c] = 0.f;
    float mrow[2][2] = {{-1e30f, -1e30f}, {-1e30f, -1e30f}};
    float lrow[2][2] = {{0.f, 0.f}, {0.f, 0.f}};

    auto prefetch = [&](int kt, int st) {
        const int k0 = kt * 64;
        __half* sk = skb + st * 4608;
        __half* sv = svb + st * 4608;
        float*  sa = alb + st * 8704;
#pragma unroll
        for (int i = 0; i < 4; i++) {
            const int idx = t + 128 * i;
            const int r = idx >> 3, c = (idx & 7) * 8;
            cp16(smem_u32(sk + r * 72 + c), kb + (size_t)(k0 + r) * HDD + c);
            cp16(smem_u32(sv + r * 72 + c), vb + (size_t)r * SS + k0 + c);
        }
#pragma unroll
        for (int i = 0; i < 16; i++) {
            const int idx = t + 128 * i;
            const int r = idx >> 4, c4 = (idx & 15) * 4;
            cp16(smem_u32(sa + r * 68 + c4),
                 ab + (size_t)(q0 + r) * SS + k0 + c4);
        }
        cp_commit();
    };

    prefetch(kt0, 0);

    for (int kt = kt0; kt < kt1; kt++) {
        const int k0 = kt * 64;
        const int st = (kt - kt0) & 1;
        if (kt + 1 < kt1) { prefetch(kt + 1, st ^ 1); cp_wait1(); }
        else              { cp_wait0(); }
        __syncthreads();

        const __half* sk = skb + st * 4608;
        const __half* sv = svb + st * 4608;
        const float*  sa = alb + st * 8704;

        float sacc[2][8][4];
#pragma unroll
        for (int i = 0; i < 2; i++)
#pragma unroll
            for (int j = 0; j < 8; j++)
#pragma unroll
                for (int c = 0; c < 4; c++) sacc[i][j][c] = 0.f;

#pragma unroll
        for (int kc = 0; kc < 4; kc++)
#pragma unroll
            for (int nt = 0; nt < 8; nt++) {
                const __half* kr = sk + (8 * nt + g) * 72 + kc * 16;
                const uint32_t b0 = *(const uint32_t*)(kr + 2 * tig);
                const uint32_t b1 = *(const uint32_t*)(kr + 8 + 2 * tig);
                mma16816h(sacc[0][nt], qf[kc][0], b0, b1);
                mma16816h(sacc[1][nt], qf[kc][1], b0, b1);
            }

#pragma unroll
        for (int mt = 0; mt < 2; mt++)
#pragma unroll
            for (int hf = 0; hf < 2; hf++) {
                const int lrowi = wm + 16 * mt + g + 8 * hf;
                const int rowg  = q0 + lrowi;
                const float* arow = sa + lrowi * 68;
                float mx = -1e30f;
#pragma unroll
                for (int nt = 0; nt < 8; nt++) {
                    const int col = k0 + 8 * nt + 2 * tig;
                    const float2 al2 = *(const float2*)(arow + 8 * nt + 2 * tig);
                    float s0 = fmaf(sacc[mt][nt][2 * hf + 0], 0.125f, al2.x);
                    float s1 = fmaf(sacc[mt][nt][2 * hf + 1], 0.125f, al2.y);
                    if (col > rowg)     s0 = -1e30f;
                    if (col + 1 > rowg) s1 = -1e30f;
                    sacc[mt][nt][2 * hf + 0] = s0;
                    sacc[mt][nt][2 * hf + 1] = s1;
                    mx = fmaxf(mx, fmaxf(s0, s1));
                }
                mx = fmaxf(mx, __shfl_xor_sync(0xffffffffu, mx, 1));
                mx = fmaxf(mx, __shfl_xor_sync(0xffffffffu, mx, 2));
                const float mn = fmaxf(mrow[mt][hf], mx);
                const float corr = __expf(mrow[mt][hf] - mn);
                mrow[mt][hf] = mn;
                lrow[mt][hf] *= corr;
#pragma unroll
                for (int nt = 0; nt < 8; nt++) {
                    o[mt][nt][2 * hf + 0] *= corr;
                    o[mt][nt][2 * hf + 1] *= corr;
                }
                float ls = 0.f;
#pragma unroll
                for (int nt = 0; nt < 8; nt++) {
                    const float p0 = __expf(sacc[mt][nt][2 * hf + 0] - mn);
                    const float p1 = __expf(sacc[mt][nt][2 * hf + 1] - mn);
                    sacc[mt][nt][2 * hf + 0] = p0;
                    sacc[mt][nt][2 * hf + 1] = p1;
                    ls += p0 + p1;
                }
                ls += __shfl_xor_sync(0xffffffffu, ls, 1);
                ls += __shfl_xor_sync(0xffffffffu, ls, 2);
                lrow[mt][hf] += ls;
            }

#pragma unroll
        for (int kc = 0; kc < 4; kc++) {
            uint32_t ap[2][4];
#pragma unroll
            for (int mt = 0; mt < 2; mt++)
#pragma unroll
                for (int q2 = 0; q2 < 2; q2++) {
                    const float* pp = sacc[mt][2 * kc + q2];
                    ap[mt][2 * q2 + 0] = pack_f16(pp[0], pp[1]);
                    ap[mt][2 * q2 + 1] = pack_f16(pp[2], pp[3]);
                }
#pragma unroll
            for (int nt = 0; nt < 8; nt++) {
                const __half* vr = sv + (8 * nt + g) * 72 + kc * 16;
                const uint32_t b0 = *(const uint32_t*)(vr + 2 * tig);
                const uint32_t b1 = *(const uint32_t*)(vr + 8 + 2 * tig);
                mma16816h(o[0][nt], ap[0], b0, b1);
                mma16816h(o[1][nt], ap[1], b0, b1);
            }
        }
        __syncthreads();
    }

    if (u >= 0) {
        float* pob = Po + (size_t)u * 128 * 64;
#pragma unroll
        for (int mt = 0; mt < 2; mt++)
#pragma unroll
            for (int hf = 0; hf < 2; hf++) {
                const int lrowi = wm + 16 * mt + g + 8 * hf;
                if (tig == 0) {
                    Pm[u * 128 + lrowi] = mrow[mt][hf];
                    Pl[u * 128 + lrowi] = lrow[mt][hf];
                }
#pragma unroll
                for (int nt = 0; nt < 8; nt++)
                    *(float2*)(pob + lrowi * 64 + 8 * nt + 2 * tig) =
                        make_float2(o[mt][nt][2 * hf + 0],
                                    o[mt][nt][2 * hf + 1]);
            }
    } else {
#pragma unroll
        for (int mt = 0; mt < 2; mt++)
#pragma unroll
            for (int hf = 0; hf < 2; hf++) {
                const float inv = 1.f / lrow[mt][hf];
                const int rowg = b * SS + q0 + wm + 16 * mt + g + 8 * hf;
#pragma unroll
                for (int nt = 0; nt < 8; nt++) {
                    const int col = h * HDD + 8 * nt + 2 * tig;
                    *(uint32_t*)(O + toff(rowg, col, DD / 32)) =
                        pack_f16(o[mt][nt][2 * hf + 0] * inv,
                                 o[mt][nt][2 * hf + 1] * inv);
                }
            }
    }
}

// ---------------------------------------------------------------------------
// split-KV merge (proven)
// ---------------------------------------------------------------------------
__global__ void __launch_bounds__(128) attn_merge(
    const float* __restrict__ Po, const float* __restrict__ Pm,
    const float* __restrict__ Pl, __half* __restrict__ O)
{
    const int v = blockIdx.x;
    const int qt = 15 - v / 24;
    const int rem = v % 24;
    const int h = rem % 12, b = rem / 12;
    const int u0 = (15 - qt) * 48 + b * 12 + h;
    const int u1 = u0 + 24;

    const int row = threadIdx.x;
    const float m1 = Pm[u0 * 128 + row], l1 = Pl[u0 * 128 + row];
    const float m2 = Pm[u1 * 128 + row], l2 = Pl[u1 * 128 + row];
    const float m  = fmaxf(m1, m2);
    const float w1 = __expf(m1 - m), w2 = __expf(m2 - m);
    const float inv = 1.f / fmaf(l1, w1, l2 * w2);
    const float a1 = w1 * inv, a2 = w2 * inv;

    const float* o1 = Po + ((size_t)u0 * 128 + row) * 64;
    const float* o2 = Po + ((size_t)u1 * 128 + row) * 64;
    const int rowg = b * SS + qt * 128 + row;
#pragma unroll
    for (int j = 0; j < 32; j++) {
        const float2 a = ((const float2*)o1)[j];
        const float2 c = ((const float2*)o2)[j];
        const float r0 = fmaf(a.x, a1, c.x * a2);
        const float r1 = fmaf(a.y, a1, c.y * a2);
        *(uint32_t*)(O + toff(rowg, h * HDD + 2 * j, DD / 32)) = pack_f16(r0, r1);
    }
}

// ---------------------------------------------------------------------------
// Fused split-K reduce + bias + residual + LayerNorm.
// SPLIT=true also writes fp32 `fout` and tiled fp16 `oh` (LN1 path);
// SPLIT=false writes only fp32 out (LN2 path -> d_out).
// ---------------------------------------------------------------------------
template <bool SPLIT>
__global__ void __launch_bounds__(256) reduce_ln(
    const float* __restrict__ p0, const float* __restrict__ p1,
    const float* __restrict__ bias, const float* __restrict__ resid,
    const float* __restrict__ gw, const float* __restrict__ bw,
    float* __restrict__ out, __half* __restrict__ oh)
{
    const int row = blockIdx.x;
    const int t   = threadIdx.x;
    const size_t base = (size_t)row * DD;

    float v[3];
#pragma unroll
    for (int j = 0; j < 3; j++) {
        const int c = t + 256 * j;
        v[j] = p0[base + c] + p1[base + c] + bias[c] + resid[base + c];
    }
    float s  = v[0] + v[1] + v[2];
    float sq = fmaf(v[0], v[0], fmaf(v[1], v[1], v[2] * v[2]));

#pragma unroll
    for (int off = 16; off; off >>= 1) {
        s  += __shfl_down_sync(0xffffffffu, s, off);
        sq += __shfl_down_sync(0xffffffffu, sq, off);
    }
    __shared__ float rs[8], rq[8];
    __shared__ float mean_s, inv_s;
    const int w = t >> 5, lane = t & 31;
    if (lane == 0) { rs[w] = s; rq[w] = sq; }
    __syncthreads();
    if (t == 0) {
        float S = 0.f, Q = 0.f;
#pragma unroll
        for (int i = 0; i < 8; i++) { S += rs[i]; Q += rq[i]; }
        const float mean = S * (1.f / 768.f);
        const float var  = Q * (1.f / 768.f) - mean * mean;
        mean_s = mean;
        inv_s  = rsqrtf(var + 1e-5f);
    }
    __syncthreads();
    const float mean = mean_s, inv = inv_s;
#pragma unroll
    for (int j = 0; j < 3; j++) {
        const int c = t + 256 * j;
        const float r = fmaf((v[j] - mean) * inv, gw[c], bw[c]);
        out[base + c] = r;
        if (SPLIT) oh[toff(row, c, DD / 32)] = __float2half_rn(r);
    }
}

// ---------------------------------------------------------------------------
// Launcher
// ---------------------------------------------------------------------------
extern "C" void kernel_launch(void* const* d_in, const int* in_sizes, int n_in,
                              void* d_out, int out_size)
{
    (void)in_sizes; (void)n_in; (void)out_size;
    const float* x     = (const float*)d_in[0];
    const float* alibi = (const float*)d_in[1];
    const float* Wq = (const float*)d_in[2];  const float* bq = (const float*)d_in[3];
    const float* Wk = (const float*)d_in[4];  const float* bk = (const float*)d_in[5];
    const float* Wv = (const float*)d_in[6];  const float* bv = (const float*)d_in[7];
    const float* Wo = (const float*)d_in[8];  const float* bo = (const float*)d_in[9];
    const float* W1 = (const float*)d_in[10]; const float* b1 = (const float*)d_in[11];
    const float* W2 = (const float*)d_in[12]; const float* b2 = (const float*)d_in[13];
    const float* g1w = (const float*)d_in[14]; const float* be1 = (const float*)d_in[15];
    const float* g2w = (const float*)d_in[16]; const float* be2 = (const float*)d_in[17];
    float* out = (float*)d_out;

    float *y, *z, *p1f, *po, *pm, *pl;
    cudaGetSymbolAddress((void**)&y,  g_y);
    cudaGetSymbolAddress((void**)&z,  g_z);
    cudaGetSymbolAddress((void**)&p1f, g_p1);
    cudaGetSymbolAddress((void**)&po, g_po);
    cudaGetSymbolAddress((void**)&pm, g_pm);
    cudaGetSymbolAddress((void**)&pl, g_pl);

    __half *xh, *ath, *yh, *h1h, *qh, *kh, *vh, *vt;
    __half *wq, *wk, *wv, *wo, *w1, *w2;
    cudaGetSymbolAddress((void**)&xh,  g_xh);
    cudaGetSymbolAddress((void**)&ath, g_ath);
    cudaGetSymbolAddress((void**)&yh,  g_yh);
    cudaGetSymbolAddress((void**)&h1h, g_h1h);
    cudaGetSymbolAddress((void**)&qh,  g_qh);
    cudaGetSymbolAddress((void**)&kh,  g_kh);
    cudaGetSymbolAddress((void**)&vh,  g_vh);
    cudaGetSymbolAddress((void**)&vt,  g_vt);
    cudaGetSymbolAddress((void**)&wq, g_wqT);
    cudaGetSymbolAddress((void**)&wk, g_wkT);
    cudaGetSymbolAddress((void**)&wv, g_wvT);
    cudaGetSymbolAddress((void**)&wo, g_woT);
    cudaGetSymbolAddress((void**)&w1, g_w1T);
    cudaGetSymbolAddress((void**)&w2, g_w2T);

    cudaFuncSetAttribute(gemm_h<M_QKV>,    cudaFuncAttributeMaxDynamicSharedMemorySize, GEMM_SMEM);
    cudaFuncSetAttribute(gemm_h<M_FF1>,    cudaFuncAttributeMaxDynamicSharedMemorySize, GEMM_SMEM);
    cudaFuncSetAttribute(gemm_h<M_SPLITK>, cudaFuncAttributeMaxDynamicSharedMemorySize, GEMM_SMEM);
    cudaFuncSetAttribute(attn_tc, cudaFuncAttributeMaxDynamicSharedMemorySize, ATTN_SMEM);

    const dim3 tb(32, 8);

    Qkv3 qkv;
    qkv.p[0] = {wq, bq, qh};
    qkv.p[1] = {wk, bk, kh};
    qkv.p[2] = {wv, bv, vh};
    Qkv3 dummy = qkv;

    T4 t4;
    t4.W[0] = Wq; t4.T[0] = wq;
    t4.W[1] = Wk; t4.T[1] = wk;
    t4.W[2] = Wv; t4.T[2] = wv;
    t4.W[3] = Wo; t4.T[3] = wo;

    // prep
    convert_h<<<3072, 256>>>(x, xh);
    transpose4_h<<<dim3(24, 24, 4), tb>>>(t4);
    transpose_h<<<dim3(96, 24), tb>>>(W1, w1, DD, DFF);
    transpose_h<<<dim3(24, 96), tb>>>(W2, w2, DFF, DD);

    // fused QKV projections
    gemm_h<M_QKV><<<dim3(6, 32, 3), 256, GEMM_SMEM>>>(
        xh, nullptr, nullptr, nullptr, nullptr, nullptr,
        qkv, NROW, DD, DD);

    vtrans_h<<<dim3(32, 24), 256>>>(vh, vt);

    // split-KV attention + merge
    attn_tc<<<576, 128, ATTN_SMEM>>>(alibi, qh, kh, vt, ath, po, pm, pl);
    attn_merge<<<192, 128>>>(po, pm, pl, ath);

    // WO: 2-way split-K -> fp32 partials, then fused reduce+residual(x)+LN1
    gemm_h<M_SPLITK><<<dim3(6, 32, 2), 256, GEMM_SMEM>>>(
        ath, wo, nullptr, nullptr, z, (__half*)p1f, dummy, NROW, DD, DD);
    reduce_ln<true><<<NROW, 256>>>(z, p1f, bo, x, g1w, be1, y, yh);

    // FF1
    gemm_h<M_FF1><<<dim3(24, 32), 256, GEMM_SMEM>>>(
        yh, w1, b1, nullptr, nullptr, h1h, dummy, NROW, DFF, DD);

    // FF2: 2-way split-K -> fp32 partials, then fused reduce+residual(y)+LN2
    gemm_h<M_SPLITK><<<dim3(6, 32, 2), 256, GEMM_SMEM>>>(
        h1h, w2, nullptr, nullptr, z, (__half*)p1f, dummy, NROW, DD, DFF);
    reduce_ln<false><<<NROW, 256>>>(z, p1f, b2, y, g2w, be2, out, nullptr);
}